// round 12
// baseline (speedup 1.0000x reference)
#include <cuda_runtime.h>
#include <cuda_fp16.h>
#include <cstdint>
#include <math.h>

// Problem constants (fixed by the dataset)
#define NNODES 102400
#define NEDGES 409600
#define HC 256
#define NH 4

// ======================= small helpers =====================================
__device__ __forceinline__ uint32_t smem_to_u32(const void* p) {
    uint32_t a;
    asm("{ .reg .u64 t; cvta.to.shared.u64 t, %1; cvt.u32.u64 %0, t; }" : "=r"(a) : "l"(p));
    return a;
}
__device__ __forceinline__ void cp16(uint32_t s, const void* g) {
    asm volatile("cp.async.cg.shared.global [%0], [%1], 16;" :: "r"(s), "l"(g));
}
__device__ __forceinline__ uint32_t lds32(uint32_t a) {
    uint32_t v; asm volatile("ld.shared.b32 %0, [%1];" : "=r"(v) : "r"(a)); return v;
}
__device__ __forceinline__ uint32_t smaddr(uint32_t base, int r, int c) {
    return base + r * 128 + ((((c >> 2) ^ (r & 7)) << 4)) + ((c & 3) << 2);
}
__device__ __forceinline__ void mma_f16(float* d, uint32_t a0, uint32_t a1, uint32_t a2,
                                        uint32_t a3, uint32_t b0, uint32_t b1) {
    asm volatile(
        "mma.sync.aligned.m16n8k16.row.col.f32.f16.f16.f32 "
        "{%0,%1,%2,%3}, {%4,%5,%6,%7}, {%8,%9}, {%0,%1,%2,%3};"
        : "+f"(d[0]), "+f"(d[1]), "+f"(d[2]), "+f"(d[3])
        : "r"(a0), "r"(a1), "r"(a2), "r"(a3), "r"(b0), "r"(b1));
}
__device__ __forceinline__ float4 leaky4_02(float4 v) {
    v.x = v.x > 0.f ? v.x : 0.2f * v.x;
    v.y = v.y > 0.f ? v.y : 0.2f * v.y;
    v.z = v.z > 0.f ? v.z : 0.2f * v.z;
    v.w = v.w > 0.f ? v.w : 0.2f * v.w;
    return v;
}

// ======================= scratch (device globals) ==========================
__device__ __align__(16) __half g_h[(size_t)NNODES * HC];   // W-transformed feats
__device__ __align__(16) __half g_A[(size_t)NNODES * HC];   // layer input (aggregated)
__device__ __align__(16) float g_als[NNODES * NH];
__device__ __align__(16) float g_ald[NNODES * NH];
__device__ int g_off[NNODES + 1];
__device__ int g_cur[NNODES];
__device__ int g_srcarr[NEDGES];
__device__ int g_is32;
__device__ __align__(16) __half g_B[600000];
__device__ __align__(16) __half g_rA[4096 * 64];
__device__ __align__(16) __half g_r1[4096 * 512];
__device__ __align__(16) __half g_r2[4096 * 512];

// B buffer element offsets (B stored [Npad][Kpad], zero padded)
#define OFF_W0  0        // 256 x 128
#define OFF_W1  32768    // 256 x 256
#define OFF_W2  98304    // 256 x 256
#define OFF_FC  163840   // 128 x 256
#define OFF_R1  196608   // 512 x 64
#define OFF_R2  229376   // 512 x 512
#define OFF_R3  491520   // 128 x 512

// ======================= edge utilities ====================================
__device__ __forceinline__ void load_edge(const void* ei, int is32, int idx,
                                          int& src, int& dst) {
    if (is32) {
        src = ((const int*)ei)[idx];
        dst = ((const int*)ei)[NEDGES + idx];
    } else {
        src = (int)((const long long*)ei)[idx];
        dst = (int)((const long long*)ei)[NEDGES + idx];
    }
}

__global__ void detect_idx_kernel(const long long* ei, int* flag) {
    int i = blockIdx.x * blockDim.x + threadIdx.x;
    if (i >= NEDGES) return;
    long long v = ei[i];
    if (v < 0 || v >= (long long)NNODES) atomicOr(flag, 1);
}

__global__ void hist_kernel(const void* __restrict__ ei, const int* __restrict__ flag,
                            int* __restrict__ counts) {
    int i = blockIdx.x * blockDim.x + threadIdx.x;
    if (i >= NEDGES) return;
    int s, d;
    load_edge(ei, *flag, i, s, d);
    atomicAdd(&counts[d], 1);
}

// single block, 1024 threads, 100 counts each (1024*100 == NNODES)
__global__ void scan_kernel(int* __restrict__ counts_cursor, int* __restrict__ offs) {
    __shared__ int part[1024];
    int t = threadIdx.x;
    int base = t * 100;
    int sum = 0;
    for (int i = 0; i < 100; i++) sum += counts_cursor[base + i];
    part[t] = sum;
    __syncthreads();
    for (int d = 1; d < 1024; d <<= 1) {
        int v = (t >= d) ? part[t - d] : 0;
        __syncthreads();
        part[t] += v;
        __syncthreads();
    }
    int run = (t == 0) ? 0 : part[t - 1];
    for (int i = 0; i < 100; i++) {
        int c = counts_cursor[base + i];
        offs[base + i] = run;
        counts_cursor[base + i] = run;   // cursor for scatter
        run += c;
    }
    if (t == 1023) offs[NNODES] = run;
}

__global__ void scatter_kernel(const void* __restrict__ ei, const int* __restrict__ flag,
                               int* __restrict__ cursor, int* __restrict__ srcarr) {
    int i = blockIdx.x * blockDim.x + threadIdx.x;
    if (i >= NEDGES) return;
    int s, d;
    load_edge(ei, *flag, i, s, d);
    int pos = atomicAdd(&cursor[d], 1);
    srcarr[pos] = s;
}

// ======================= misc conversions ==================================
__global__ void conv_A_kernel(const float* __restrict__ A, __half* __restrict__ out,
                              int M, int K, int Kpad) {
    int i = blockIdx.x * blockDim.x + threadIdx.x;
    if (i >= M * Kpad) return;
    int m = i / Kpad, k = i - m * Kpad;
    float v = (k < K) ? A[(size_t)m * K + k] : 0.f;
    out[i] = __float2half(v);
}

// All weight tables converted in ONE launch. B [K,N] fp32 row-major ->
// Bt [Npad, Kpad] fp16 (zero padded), per-segment descriptors.
struct ConvDesc { const float* src; int K, N, Kpad, dstOff, base, elems; };
struct ConvTable { ConvDesc d[7]; int total; };
__global__ void conv_B_all(ConvTable t, __half* __restrict__ out) {
    int i = blockIdx.x * blockDim.x + threadIdx.x;
    if (i >= t.total) return;
    int seg = 0;
#pragma unroll
    for (int q = 0; q < 6; q++)
        if (i >= t.d[q].base + t.d[q].elems) seg = q + 1;
    const ConvDesc& dd = t.d[seg];
    int local = i - dd.base;
    int n = local / dd.Kpad, k = local - n * dd.Kpad;
    float v = (k < dd.K && n < dd.N) ? dd.src[(size_t)k * dd.N + n] : 0.f;
    out[dd.dstOff + local] = __float2half(v);
}

// ======================= fp16 mma.sync GEMM ================================
// 512 threads = 16 warps (4 warpM x 4 warpN), warp tile 32 x (N8*8).
// CTA tile 128 x NBLK (NBLK = N8*32). K chunks of 64, 3-stage cp.async.
// N8=8: NBLK=256 (layer GEMMs, fused attn logits). N8=4: NBLK=128 (fc, r3).
template<int N8>
__global__ __launch_bounds__(512, 1)
void gemm_mma(const __half* __restrict__ A, int Kpad, const __half* __restrict__ B,
              float* outf, __half* outh, int nwrite, int ldout,
              const float* __restrict__ bias, int act,
              const float* __restrict__ a_src, const float* __restrict__ a_dst,
              float* als, float* ald)
{
    constexpr int NBLK = N8 * 32;
    constexpr uint32_t ASTAGE = 16384u;                 // 128 rows x 128B
    constexpr uint32_t BSTAGE = (uint32_t)NBLK * 128u;
    constexpr uint32_t STAGE = ASTAGE + BSTAGE;
    extern __shared__ char sm_raw[];
    uint32_t sb = smem_to_u32(sm_raw);
    int tid = threadIdx.x, wid = tid >> 5, lane = tid & 31;
    int warpM = wid & 3, warpN = wid >> 2;
    int mBase = blockIdx.x * 128;
    int nBase = blockIdx.y * NBLK;
    const int NC = Kpad >> 6;
    const int kp = lane & 3;
    const int lq = lane >> 2;

    float acc[2][N8][4];
#pragma unroll
    for (int i = 0; i < 2; i++)
#pragma unroll
        for (int j = 0; j < N8; j++)
#pragma unroll
            for (int q = 0; q < 4; q++) acc[i][j][q] = 0.f;

    // stage loader
    auto load_stage = [&](int stage, int chunk) {
        uint32_t base = sb + (uint32_t)stage * STAGE;
        int ko = chunk * 64;
#pragma unroll
        for (int i = 0; i < 2; i++) {                 // A: 1024 granules
            int u = tid + i * 512;
            int row = u >> 3, g = u & 7;
            const __half* src = A + (size_t)(mBase + row) * Kpad + ko + g * 8;
            cp16(base + row * 128 + (((g ^ (row & 7)) << 4)), src);
        }
        for (int u = tid; u < NBLK * 8; u += 512) {   // B granules
            int row = u >> 3, g = u & 7;
            const __half* src = B + (size_t)(nBase + row) * Kpad + ko + g * 8;
            cp16(base + ASTAGE + row * 128 + (((g ^ (row & 7)) << 4)), src);
        }
        asm volatile("cp.async.commit_group;" ::: "memory");
    };

    // ---- prologue: stages 0 and (if present) 1 ----
    load_stage(0, 0);
    if (NC > 1) load_stage(1, 1);

    for (int c = 0; c < NC; c++) {
        if (c + 2 < NC) {
            load_stage((c + 2) % 3, c + 2);           // stage == (c-1)%3, free since last iter's sync
            asm volatile("cp.async.wait_group 2;" ::: "memory");
        } else if (c + 1 < NC) {
            asm volatile("cp.async.wait_group 1;" ::: "memory");
        } else {
            asm volatile("cp.async.wait_group 0;" ::: "memory");
        }
        __syncthreads();

        uint32_t aB = sb + (uint32_t)(c % 3) * STAGE;
        uint32_t bB = aB + ASTAGE;
#pragma unroll
        for (int k16 = 0; k16 < 4; k16++) {
            int c0 = k16 * 8;
            uint32_t Af[2][4];
#pragma unroll
            for (int mf = 0; mf < 2; mf++) {
                int r0 = warpM * 32 + mf * 16 + lq;
                Af[mf][0] = lds32(smaddr(aB, r0,     c0 + kp));
                Af[mf][1] = lds32(smaddr(aB, r0 + 8, c0 + kp));
                Af[mf][2] = lds32(smaddr(aB, r0,     c0 + kp + 4));
                Af[mf][3] = lds32(smaddr(aB, r0 + 8, c0 + kp + 4));
            }
#pragma unroll
            for (int n8 = 0; n8 < N8; n8++) {
                int n = warpN * N8 * 8 + n8 * 8 + lq;
                uint32_t b0 = lds32(smaddr(bB, n, c0 + kp));
                uint32_t b1 = lds32(smaddr(bB, n, c0 + kp + 4));
#pragma unroll
                for (int mf = 0; mf < 2; mf++)
                    mma_f16(acc[mf][n8], Af[mf][0], Af[mf][1], Af[mf][2], Af[mf][3], b0, b1);
            }
        }
        __syncthreads();
    }

    // ---- epilogue ----
    int limit = nwrite - nBase;
    float s1[2][2] = {{0.f, 0.f}, {0.f, 0.f}};
    float s2[2][2] = {{0.f, 0.f}, {0.f, 0.f}};
#pragma unroll
    for (int mf = 0; mf < 2; mf++) {
        int gr0 = mBase + warpM * 32 + mf * 16 + lq;
#pragma unroll
        for (int n8 = 0; n8 < N8; n8++) {
            int cl = warpN * N8 * 8 + n8 * 8 + kp * 2;
            float v[4];
#pragma unroll
            for (int q = 0; q < 4; q++) v[q] = acc[mf][n8][q];
#pragma unroll
            for (int q = 0; q < 4; q++) {
                int col = cl + (q & 1);
                if (col < limit) {
                    float x = v[q];
                    if (bias) x += bias[nBase + col];
                    if (act) x = x > 0.f ? x : 0.01f * x;
                    v[q] = x;
                }
            }
            if (a_src) {
                s1[mf][0] += v[0] * a_src[cl] + v[1] * a_src[cl + 1];
                s2[mf][0] += v[0] * a_dst[cl] + v[1] * a_dst[cl + 1];
                s1[mf][1] += v[2] * a_src[cl] + v[3] * a_src[cl + 1];
                s2[mf][1] += v[2] * a_dst[cl] + v[3] * a_dst[cl + 1];
            }
            if (outf) {
                if (cl + 1 < limit) {
                    *(float2*)(outf + (size_t)gr0 * ldout + nBase + cl) = make_float2(v[0], v[1]);
                    *(float2*)(outf + (size_t)(gr0 + 8) * ldout + nBase + cl) = make_float2(v[2], v[3]);
                } else if (cl < limit) {
                    outf[(size_t)gr0 * ldout + nBase + cl] = v[0];
                    outf[(size_t)(gr0 + 8) * ldout + nBase + cl] = v[2];
                }
            }
            if (outh && cl < limit) {
                *(__half2*)(outh + (size_t)gr0 * ldout + nBase + cl) = __floats2half2_rn(v[0], v[1]);
                *(__half2*)(outh + (size_t)(gr0 + 8) * ldout + nBase + cl) = __floats2half2_rn(v[2], v[3]);
            }
        }
    }
    if (a_src) {
        // warpN == head (N8 == 8: warp covers 64 cols == one head)
#pragma unroll
        for (int mf = 0; mf < 2; mf++)
#pragma unroll
            for (int hf = 0; hf < 2; hf++) {
                s1[mf][hf] += __shfl_xor_sync(0xFFFFFFFF, s1[mf][hf], 1);
                s1[mf][hf] += __shfl_xor_sync(0xFFFFFFFF, s1[mf][hf], 2);
                s2[mf][hf] += __shfl_xor_sync(0xFFFFFFFF, s2[mf][hf], 1);
                s2[mf][hf] += __shfl_xor_sync(0xFFFFFFFF, s2[mf][hf], 2);
            }
        if ((lane & 3) == 0) {
#pragma unroll
            for (int mf = 0; mf < 2; mf++)
#pragma unroll
                for (int hf = 0; hf < 2; hf++) {
                    int gr = mBase + warpM * 32 + mf * 16 + hf * 8 + lq;
                    als[gr * 4 + warpN] = s1[mf][hf];
                    ald[gr * 4 + warpN] = s2[mf][hf];
                }
        }
    }
}

// ======================= fused GAT aggregation (one warp per dst) ==========
// h is fp16 (L2-resident). Lane l handles channels [8l, 8(l+1)); head = l>>3.
// First 32 edges' (src, e) cached in registers from pass 1 (avg degree = 4,
// so pass 2's random als4 reloads vanish for nearly all nodes).
__global__ __launch_bounds__(256)
void gat_agg(const int* __restrict__ offs, const int* __restrict__ srcarr,
             const float4* __restrict__ als4, const float4* __restrict__ ald4,
             const __half* __restrict__ h,
             const float* __restrict__ bias, int act,
             __half* __restrict__ out)
{
    __shared__ int    sh_src[8][32];
    __shared__ float4 sh_p[8][32];
    int w = (blockIdx.x * blockDim.x + threadIdx.x) >> 5;
    int ww = (threadIdx.x >> 5);
    int lane = threadIdx.x & 31;
    if (w >= NNODES) return;
    int n = w;
    int head = lane >> 3;
    int beg = offs[n], end = offs[n + 1];
    float4 aldn = ald4[n];
    float4 an = als4[n];
    float4 eself = leaky4_02(make_float4(an.x + aldn.x, an.y + aldn.y,
                                         an.z + aldn.z, an.w + aldn.w));
    // ---- pass 1: segment max, caching the first chunk's (src, e) ----
    float4 m = eself;
    int s_first = 0;
    float4 e_first = make_float4(0.f, 0.f, 0.f, 0.f);
    {
        int j = beg + lane;
        if (j < end) {
            s_first = srcarr[j];
            float4 a = als4[s_first];
            e_first = leaky4_02(make_float4(a.x + aldn.x, a.y + aldn.y,
                                            a.z + aldn.z, a.w + aldn.w));
            m.x = fmaxf(m.x, e_first.x); m.y = fmaxf(m.y, e_first.y);
            m.z = fmaxf(m.z, e_first.z); m.w = fmaxf(m.w, e_first.w);
        }
        for (j += 32; j < end; j += 32) {
            int s = srcarr[j];
            float4 a = als4[s];
            float4 e = leaky4_02(make_float4(a.x + aldn.x, a.y + aldn.y,
                                             a.z + aldn.z, a.w + aldn.w));
            m.x = fmaxf(m.x, e.x); m.y = fmaxf(m.y, e.y);
            m.z = fmaxf(m.z, e.z); m.w = fmaxf(m.w, e.w);
        }
    }
#pragma unroll
    for (int o = 16; o; o >>= 1) {
        m.x = fmaxf(m.x, __shfl_xor_sync(0xFFFFFFFF, m.x, o));
        m.y = fmaxf(m.y, __shfl_xor_sync(0xFFFFFFFF, m.y, o));
        m.z = fmaxf(m.z, __shfl_xor_sync(0xFFFFFFFF, m.z, o));
        m.w = fmaxf(m.w, __shfl_xor_sync(0xFFFFFFFF, m.w, o));
    }
    // ---- pass 2: p, sum, gather-accumulate (one uint4 = 8 halfs per lane) --
    float acc[8] = {0.f, 0.f, 0.f, 0.f, 0.f, 0.f, 0.f, 0.f};
    float4 psum = make_float4(0.f, 0.f, 0.f, 0.f);
    for (int base = beg; base < end; base += 32) {
        int j = base + lane;
        int valid = j < end;
        int s = 0;
        float4 p = make_float4(0.f, 0.f, 0.f, 0.f);
        if (valid) {
            float4 e;
            if (base == beg) {            // cached from pass 1
                s = s_first;
                e = e_first;
            } else {
                s = srcarr[j];
                float4 a = als4[s];
                e = leaky4_02(make_float4(a.x + aldn.x, a.y + aldn.y,
                                          a.z + aldn.z, a.w + aldn.w));
            }
            p.x = __expf(e.x - m.x); p.y = __expf(e.y - m.y);
            p.z = __expf(e.z - m.z); p.w = __expf(e.w - m.w);
            psum.x += p.x; psum.y += p.y; psum.z += p.z; psum.w += p.w;
        }
        sh_src[ww][lane] = s;
        sh_p[ww][lane] = p;
        __syncwarp();
        int cnt = end - base; if (cnt > 32) cnt = 32;
#pragma unroll 4
        for (int jj = 0; jj < cnt; jj++) {
            int sj = sh_src[ww][jj];
            float4 pj = sh_p[ww][jj];
            float pv = (head == 0) ? pj.x : (head == 1) ? pj.y : (head == 2) ? pj.z : pj.w;
            uint4 raw = __ldg((const uint4*)(h + (size_t)sj * HC) + lane);
            float2 f0 = __half22float2(*(__half2*)&raw.x);
            float2 f1 = __half22float2(*(__half2*)&raw.y);
            float2 f2 = __half22float2(*(__half2*)&raw.z);
            float2 f3 = __half22float2(*(__half2*)&raw.w);
            acc[0] += pv * f0.x; acc[1] += pv * f0.y;
            acc[2] += pv * f1.x; acc[3] += pv * f1.y;
            acc[4] += pv * f2.x; acc[5] += pv * f2.y;
            acc[6] += pv * f3.x; acc[7] += pv * f3.y;
        }
        __syncwarp();
    }
#pragma unroll
    for (int o = 16; o; o >>= 1) {
        psum.x += __shfl_xor_sync(0xFFFFFFFF, psum.x, o);
        psum.y += __shfl_xor_sync(0xFFFFFFFF, psum.y, o);
        psum.z += __shfl_xor_sync(0xFFFFFFFF, psum.z, o);
        psum.w += __shfl_xor_sync(0xFFFFFFFF, psum.w, o);
    }
    // self loop contribution
    float4 ps;
    ps.x = __expf(eself.x - m.x); ps.y = __expf(eself.y - m.y);
    ps.z = __expf(eself.z - m.z); ps.w = __expf(eself.w - m.w);
    psum.x += ps.x; psum.y += ps.y; psum.z += ps.z; psum.w += ps.w;
    {
        float pv = (head == 0) ? ps.x : (head == 1) ? ps.y : (head == 2) ? ps.z : ps.w;
        uint4 raw = __ldg((const uint4*)(h + (size_t)n * HC) + lane);
        float2 f0 = __half22float2(*(__half2*)&raw.x);
        float2 f1 = __half22float2(*(__half2*)&raw.y);
        float2 f2 = __half22float2(*(__half2*)&raw.z);
        float2 f3 = __half22float2(*(__half2*)&raw.w);
        acc[0] += pv * f0.x; acc[1] += pv * f0.y;
        acc[2] += pv * f1.x; acc[3] += pv * f1.y;
        acc[4] += pv * f2.x; acc[5] += pv * f2.y;
        acc[6] += pv * f3.x; acc[7] += pv * f3.y;
    }
    // ---- epilogue: divide, bias, act, write fp16 ----
    float sH = (head == 0) ? psum.x : (head == 1) ? psum.y : (head == 2) ? psum.z : psum.w;
    float r = 1.f / sH;
    const float4* b4 = (const float4*)bias;   // channels 8l..8l+8 = b4[2l], b4[2l+1]
    float4 bA = b4[lane * 2], bB = b4[lane * 2 + 1];
    float v[8];
    v[0] = acc[0] * r + bA.x; v[1] = acc[1] * r + bA.y;
    v[2] = acc[2] * r + bA.z; v[3] = acc[3] * r + bA.w;
    v[4] = acc[4] * r + bB.x; v[5] = acc[5] * r + bB.y;
    v[6] = acc[6] * r + bB.z; v[7] = acc[7] * r + bB.w;
    if (act) {
#pragma unroll
        for (int q = 0; q < 8; q++) v[q] = v[q] > 0.f ? v[q] : 0.01f * v[q];
    }
    uint4 pack;
    *(__half2*)&pack.x = __floats2half2_rn(v[0], v[1]);
    *(__half2*)&pack.y = __floats2half2_rn(v[2], v[3]);
    *(__half2*)&pack.z = __floats2half2_rn(v[4], v[5]);
    *(__half2*)&pack.w = __floats2half2_rn(v[6], v[7]);
    *((uint4*)(out + (size_t)n * HC) + lane) = pack;
}

// ======================= host orchestration ================================
#define SMEM_N8  (3 * (16384 + 256 * 128))   // 147456
#define SMEM_N4  (3 * (16384 + 128 * 128))   // 98304

extern "C" void kernel_launch(void* const* d_in, const int* in_sizes, int n_in,
                              void* d_out, int out_size)
{
    const float* x    = (const float*)d_in[0];
    const void*  ei   = d_in[1];
    const float* root = (const float*)d_in[2];
    const float* W[3]  = {(const float*)d_in[3], (const float*)d_in[7],  (const float*)d_in[11]};
    const float* aS[3] = {(const float*)d_in[4], (const float*)d_in[8],  (const float*)d_in[12]};
    const float* aD[3] = {(const float*)d_in[5], (const float*)d_in[9],  (const float*)d_in[13]};
    const float* bb[3] = {(const float*)d_in[6], (const float*)d_in[10], (const float*)d_in[14]};
    const float* fc_w = (const float*)d_in[15];
    const float* fc_b = (const float*)d_in[16];
    const float* r_w1 = (const float*)d_in[17];
    const float* r_b1 = (const float*)d_in[18];
    const float* r_w2 = (const float*)d_in[19];
    const float* r_b2 = (const float*)d_in[20];
    const float* r_w3 = (const float*)d_in[21];
    const float* r_b3 = (const float*)d_in[22];

    float *p_als, *p_ald;
    __half *p_h, *p_A, *p_B, *p_rA, *p_r1, *p_r2;
    int *p_off, *p_cur, *p_srcarr, *p_flag;
    cudaGetSymbolAddress((void**)&p_h,   g_h);
    cudaGetSymbolAddress((void**)&p_A,   g_A);
    cudaGetSymbolAddress((void**)&p_als, g_als);
    cudaGetSymbolAddress((void**)&p_ald, g_ald);
    cudaGetSymbolAddress((void**)&p_off, g_off);
    cudaGetSymbolAddress((void**)&p_cur, g_cur);
    cudaGetSymbolAddress((void**)&p_srcarr, g_srcarr);
    cudaGetSymbolAddress((void**)&p_flag, g_is32);
    cudaGetSymbolAddress((void**)&p_B,   g_B);
    cudaGetSymbolAddress((void**)&p_rA,  g_rA);
    cudaGetSymbolAddress((void**)&p_r1,  g_r1);
    cudaGetSymbolAddress((void**)&p_r2,  g_r2);

    static int smem_set = 0;
    if (!smem_set) {
        cudaFuncSetAttribute(gemm_mma<8>, cudaFuncAttributeMaxDynamicSharedMemorySize, SMEM_N8);
        cudaFuncSetAttribute(gemm_mma<4>, cudaFuncAttributeMaxDynamicSharedMemorySize, SMEM_N4);
        smem_set = 1;
    }

    // ---- CSR build (once per call, reused by all 3 layers) ----
    cudaMemsetAsync(p_flag, 0, sizeof(int));
    detect_idx_kernel<<<(NEDGES + 255) / 256, 256>>>((const long long*)ei, p_flag);
    cudaMemsetAsync(p_cur, 0, NNODES * sizeof(int));
    hist_kernel<<<(NEDGES + 255) / 256, 256>>>(ei, p_flag, p_cur);
    scan_kernel<<<1, 1024>>>(p_cur, p_off);
    scatter_kernel<<<(NEDGES + 255) / 256, 256>>>(ei, p_flag, p_cur, p_srcarr);

    // ---- weight conversions (single launch) ----
    {
        ConvTable t;
        int base = 0;
        const float* srcs[7] = {W[0], W[1], W[2], fc_w, r_w1, r_w2, r_w3};
        int Ks[7]    = {80, 256, 256, 256, 60, 512, 512};
        int Ns[7]    = {256, 256, 256, 80, 512, 512, 60};
        int Kpads[7] = {128, 256, 256, 256, 64, 512, 512};
        int Npads[7] = {256, 256, 256, 128, 512, 512, 128};
        int offs7[7] = {OFF_W0, OFF_W1, OFF_W2, OFF_FC, OFF_R1, OFF_R2, OFF_R3};
        for (int i = 0; i < 7; i++) {
            t.d[i].src = srcs[i]; t.d[i].K = Ks[i]; t.d[i].N = Ns[i];
            t.d[i].Kpad = Kpads[i]; t.d[i].dstOff = offs7[i];
            t.d[i].base = base; t.d[i].elems = Npads[i] * Kpads[i];
            base += t.d[i].elems;
        }
        t.total = base;
        conv_B_all<<<(t.total + 255) / 256, 256>>>(t, p_B);
    }

    // x -> fp16, K padded 80->128
    conv_A_kernel<<<(NNODES * 128 + 255) / 256, 256>>>(x, p_A, NNODES, 80, 128);

    const int Kpad[3] = {128, 256, 256};
    const __half* Boff[3] = {p_B + OFF_W0, p_B + OFF_W1, p_B + OFF_W2};

    for (int L = 0; L < 3; L++) {
        gemm_mma<8><<<dim3(NNODES / 128, 1), 512, SMEM_N8>>>(
            p_A, Kpad[L], Boff[L],
            nullptr, p_h, 256, 256,
            nullptr, 0, aS[L], aD[L], p_als, p_ald);
        int act = (L < 2) ? 1 : 0;
        gat_agg<<<NNODES / 8, 256>>>(p_off, p_srcarr,
                                     (const float4*)p_als, (const float4*)p_ald,
                                     p_h, bb[L], act, p_A);
    }

    // rot = h @ fc_w + fc_b -> d_out[0 : N*80]  (NBLK=128, only 80 valid)
    float* rot = (float*)d_out;
    gemm_mma<4><<<dim3(NNODES / 128, 1), 512, SMEM_N4>>>(
        p_A, 256, p_B + OFF_FC,
        rot, nullptr, 80, 80,
        fc_b, 0, nullptr, nullptr, nullptr, nullptr);

    // root MLP
    conv_A_kernel<<<(4096 * 64 + 255) / 256, 256>>>(root, p_rA, 4096, 60, 64);
    gemm_mma<8><<<dim3(32, 2), 512, SMEM_N8>>>(
        p_rA, 64, p_B + OFF_R1,
        nullptr, p_r1, 512, 512,
        r_b1, 1, nullptr, nullptr, nullptr, nullptr);
    gemm_mma<8><<<dim3(32, 2), 512, SMEM_N8>>>(
        p_r1, 512, p_B + OFF_R2,
        nullptr, p_r2, 512, 512,
        r_b2, 1, nullptr, nullptr, nullptr, nullptr);
    float* root_out = rot + (size_t)NNODES * 80;
    gemm_mma<4><<<dim3(32, 1), 512, SMEM_N4>>>(
        p_r2, 512, p_B + OFF_R3,
        root_out, nullptr, 60, 60,
        r_b3, 0, nullptr, nullptr, nullptr, nullptr);
}

// round 13
// speedup vs baseline: 1.0703x; 1.0703x over previous
#include <cuda_runtime.h>
#include <cuda_fp16.h>
#include <cstdint>
#include <math.h>

// Problem constants (fixed by the dataset)
#define NNODES 102400
#define NEDGES 409600
#define HC 256
#define NH 4

// ======================= small helpers =====================================
__device__ __forceinline__ uint32_t smem_to_u32(const void* p) {
    uint32_t a;
    asm("{ .reg .u64 t; cvta.to.shared.u64 t, %1; cvt.u32.u64 %0, t; }" : "=r"(a) : "l"(p));
    return a;
}
__device__ __forceinline__ void cp16(uint32_t s, const void* g) {
    asm volatile("cp.async.cg.shared.global [%0], [%1], 16;" :: "r"(s), "l"(g));
}
__device__ __forceinline__ uint32_t lds32(uint32_t a) {
    uint32_t v; asm volatile("ld.shared.b32 %0, [%1];" : "=r"(v) : "r"(a)); return v;
}
__device__ __forceinline__ uint32_t smaddr(uint32_t base, int r, int c) {
    return base + r * 128 + ((((c >> 2) ^ (r & 7)) << 4)) + ((c & 3) << 2);
}
__device__ __forceinline__ void mma_f16(float* d, uint32_t a0, uint32_t a1, uint32_t a2,
                                        uint32_t a3, uint32_t b0, uint32_t b1) {
    asm volatile(
        "mma.sync.aligned.m16n8k16.row.col.f32.f16.f16.f32 "
        "{%0,%1,%2,%3}, {%4,%5,%6,%7}, {%8,%9}, {%0,%1,%2,%3};"
        : "+f"(d[0]), "+f"(d[1]), "+f"(d[2]), "+f"(d[3])
        : "r"(a0), "r"(a1), "r"(a2), "r"(a3), "r"(b0), "r"(b1));
}
__device__ __forceinline__ float4 leaky4_02(float4 v) {
    v.x = v.x > 0.f ? v.x : 0.2f * v.x;
    v.y = v.y > 0.f ? v.y : 0.2f * v.y;
    v.z = v.z > 0.f ? v.z : 0.2f * v.z;
    v.w = v.w > 0.f ? v.w : 0.2f * v.w;
    return v;
}

// ======================= scratch (device globals) ==========================
__device__ __align__(16) __half g_h[(size_t)NNODES * HC];   // W-transformed feats
__device__ __align__(16) __half g_A[(size_t)NNODES * HC];   // layer input (aggregated)
__device__ __align__(16) float g_als[NNODES * NH];
__device__ __align__(16) float g_ald[NNODES * NH];
__device__ int g_off[NNODES + 1];
__device__ int g_cur[NNODES];
__device__ int g_srcarr[NEDGES];
__device__ int g_is32;
__device__ __align__(16) __half g_B[600000];
__device__ __align__(16) __half g_rA[4096 * 64];
__device__ __align__(16) __half g_r1[4096 * 512];
__device__ __align__(16) __half g_r2[4096 * 512];

// B buffer element offsets (B stored [Npad][Kpad], zero padded)
#define OFF_W0  0        // 256 x 128
#define OFF_W1  32768    // 256 x 256
#define OFF_W2  98304    // 256 x 256
#define OFF_FC  163840   // 128 x 256
#define OFF_R1  196608   // 512 x 64
#define OFF_R2  229376   // 512 x 512
#define OFF_R3  491520   // 128 x 512

// ======================= edge utilities ====================================
__device__ __forceinline__ void load_edge(const void* ei, int is32, int idx,
                                          int& src, int& dst) {
    if (is32) {
        src = ((const int*)ei)[idx];
        dst = ((const int*)ei)[NEDGES + idx];
    } else {
        src = (int)((const long long*)ei)[idx];
        dst = (int)((const long long*)ei)[NEDGES + idx];
    }
}

__global__ void detect_idx_kernel(const long long* ei, int* flag) {
    int i = blockIdx.x * blockDim.x + threadIdx.x;
    if (i >= NEDGES) return;
    long long v = ei[i];
    if (v < 0 || v >= (long long)NNODES) atomicOr(flag, 1);
}

__global__ void hist_kernel(const void* __restrict__ ei, const int* __restrict__ flag,
                            int* __restrict__ counts) {
    int i = blockIdx.x * blockDim.x + threadIdx.x;
    if (i >= NEDGES) return;
    int s, d;
    load_edge(ei, *flag, i, s, d);
    atomicAdd(&counts[d], 1);
}

// single block, 1024 threads, 100 counts each (1024*100 == NNODES)
__global__ void scan_kernel(int* __restrict__ counts_cursor, int* __restrict__ offs) {
    __shared__ int part[1024];
    int t = threadIdx.x;
    int base = t * 100;
    int sum = 0;
    for (int i = 0; i < 100; i++) sum += counts_cursor[base + i];
    part[t] = sum;
    __syncthreads();
    for (int d = 1; d < 1024; d <<= 1) {
        int v = (t >= d) ? part[t - d] : 0;
        __syncthreads();
        part[t] += v;
        __syncthreads();
    }
    int run = (t == 0) ? 0 : part[t - 1];
    for (int i = 0; i < 100; i++) {
        int c = counts_cursor[base + i];
        offs[base + i] = run;
        counts_cursor[base + i] = run;   // cursor for scatter
        run += c;
    }
    if (t == 1023) offs[NNODES] = run;
}

__global__ void scatter_kernel(const void* __restrict__ ei, const int* __restrict__ flag,
                               int* __restrict__ cursor, int* __restrict__ srcarr) {
    int i = blockIdx.x * blockDim.x + threadIdx.x;
    if (i >= NEDGES) return;
    int s, d;
    load_edge(ei, *flag, i, s, d);
    int pos = atomicAdd(&cursor[d], 1);
    srcarr[pos] = s;
}

// ======================= misc conversions ==================================
__global__ void conv_A_kernel(const float* __restrict__ A, __half* __restrict__ out,
                              int M, int K, int Kpad) {
    int i = blockIdx.x * blockDim.x + threadIdx.x;
    if (i >= M * Kpad) return;
    int m = i / Kpad, k = i - m * Kpad;
    float v = (k < K) ? A[(size_t)m * K + k] : 0.f;
    out[i] = __float2half(v);
}

// All weight tables converted in ONE launch. B [K,N] fp32 row-major ->
// Bt [Npad, Kpad] fp16 (zero padded), per-segment descriptors.
struct ConvDesc { const float* src; int K, N, Kpad, dstOff, base, elems; };
struct ConvTable { ConvDesc d[7]; int total; };
__global__ void conv_B_all(ConvTable t, __half* __restrict__ out) {
    int i = blockIdx.x * blockDim.x + threadIdx.x;
    if (i >= t.total) return;
    int seg = 0;
#pragma unroll
    for (int q = 0; q < 6; q++)
        if (i >= t.d[q].base + t.d[q].elems) seg = q + 1;
    const ConvDesc& dd = t.d[seg];
    int local = i - dd.base;
    int n = local / dd.Kpad, k = local - n * dd.Kpad;
    float v = (k < dd.K && n < dd.N) ? dd.src[(size_t)k * dd.N + n] : 0.f;
    out[dd.dstOff + local] = __float2half(v);
}

// ======================= fp16 mma.sync GEMM (R10 config) ===================
// 512 threads = 16 warps (4 warpM x 4 warpN), warp tile 32 x (N8*8).
// CTA tile 128 x NBLK (NBLK = N8*32). K chunks of 64, double buffered.
// N8=8: NBLK=256 (layer GEMMs, fused attn logits). N8=4: NBLK=128 (fc, r3).
template<int N8>
__global__ __launch_bounds__(512, 1)
void gemm_mma(const __half* __restrict__ A, int Kpad, const __half* __restrict__ B,
              float* outf, __half* outh, int nwrite, int ldout,
              const float* __restrict__ bias, int act,
              const float* __restrict__ a_src, const float* __restrict__ a_dst,
              float* als, float* ald)
{
    constexpr int NBLK = N8 * 32;
    constexpr uint32_t ASTAGE = 16384u;                 // 128 rows x 128B
    constexpr uint32_t BSTAGE = (uint32_t)NBLK * 128u;
    constexpr uint32_t STAGE = ASTAGE + BSTAGE;
    extern __shared__ char sm_raw[];
    uint32_t sb = smem_to_u32(sm_raw);
    int tid = threadIdx.x, wid = tid >> 5, lane = tid & 31;
    int warpM = wid & 3, warpN = wid >> 2;
    int mBase = blockIdx.x * 128;
    int nBase = blockIdx.y * NBLK;
    const int NC = Kpad >> 6;
    const int kp = lane & 3;
    const int lq = lane >> 2;

    float acc[2][N8][4];
#pragma unroll
    for (int i = 0; i < 2; i++)
#pragma unroll
        for (int j = 0; j < N8; j++)
#pragma unroll
            for (int q = 0; q < 4; q++) acc[i][j][q] = 0.f;

    // ---- prologue: stage 0 ----
    {
        uint32_t base = sb;
#pragma unroll
        for (int i = 0; i < 2; i++) {                 // A: 1024 granules
            int u = tid + i * 512;
            int row = u >> 3, g = u & 7;
            const __half* src = A + (size_t)(mBase + row) * Kpad + g * 8;
            cp16(base + row * 128 + (((g ^ (row & 7)) << 4)), src);
        }
        for (int u = tid; u < NBLK * 8; u += 512) {   // B granules
            int row = u >> 3, g = u & 7;
            const __half* src = B + (size_t)(nBase + row) * Kpad + g * 8;
            cp16(base + ASTAGE + row * 128 + (((g ^ (row & 7)) << 4)), src);
        }
        asm volatile("cp.async.commit_group;" ::: "memory");
    }

    for (int c = 0; c < NC; c++) {
        if (c + 1 < NC) {
            uint32_t base = sb + ((c + 1) & 1) * STAGE;
            int ko = (c + 1) * 64;
#pragma unroll
            for (int i = 0; i < 2; i++) {
                int u = tid + i * 512;
                int row = u >> 3, g = u & 7;
                const __half* src = A + (size_t)(mBase + row) * Kpad + ko + g * 8;
                cp16(base + row * 128 + (((g ^ (row & 7)) << 4)), src);
            }
            for (int u = tid; u < NBLK * 8; u += 512) {
                int row = u >> 3, g = u & 7;
                const __half* src = B + (size_t)(nBase + row) * Kpad + ko + g * 8;
                cp16(base + ASTAGE + row * 128 + (((g ^ (row & 7)) << 4)), src);
            }
            asm volatile("cp.async.commit_group;" ::: "memory");
            asm volatile("cp.async.wait_group 1;" ::: "memory");
        } else {
            asm volatile("cp.async.wait_group 0;" ::: "memory");
        }
        __syncthreads();

        uint32_t aB = sb + (c & 1) * STAGE;
        uint32_t bB = aB + ASTAGE;
#pragma unroll
        for (int k16 = 0; k16 < 4; k16++) {
            int c0 = k16 * 8;
            uint32_t Af[2][4];
#pragma unroll
            for (int mf = 0; mf < 2; mf++) {
                int r0 = warpM * 32 + mf * 16 + lq;
                Af[mf][0] = lds32(smaddr(aB, r0,     c0 + kp));
                Af[mf][1] = lds32(smaddr(aB, r0 + 8, c0 + kp));
                Af[mf][2] = lds32(smaddr(aB, r0,     c0 + kp + 4));
                Af[mf][3] = lds32(smaddr(aB, r0 + 8, c0 + kp + 4));
            }
#pragma unroll
            for (int n8 = 0; n8 < N8; n8++) {
                int n = warpN * N8 * 8 + n8 * 8 + lq;
                uint32_t b0 = lds32(smaddr(bB, n, c0 + kp));
                uint32_t b1 = lds32(smaddr(bB, n, c0 + kp + 4));
#pragma unroll
                for (int mf = 0; mf < 2; mf++)
                    mma_f16(acc[mf][n8], Af[mf][0], Af[mf][1], Af[mf][2], Af[mf][3], b0, b1);
            }
        }
        __syncthreads();
    }

    // ---- epilogue ----
    int limit = nwrite - nBase;
    float s1[2][2] = {{0.f, 0.f}, {0.f, 0.f}};
    float s2[2][2] = {{0.f, 0.f}, {0.f, 0.f}};
#pragma unroll
    for (int mf = 0; mf < 2; mf++) {
        int gr0 = mBase + warpM * 32 + mf * 16 + lq;
#pragma unroll
        for (int n8 = 0; n8 < N8; n8++) {
            int cl = warpN * N8 * 8 + n8 * 8 + kp * 2;
            float v[4];
#pragma unroll
            for (int q = 0; q < 4; q++) v[q] = acc[mf][n8][q];
#pragma unroll
            for (int q = 0; q < 4; q++) {
                int col = cl + (q & 1);
                if (col < limit) {
                    float x = v[q];
                    if (bias) x += bias[nBase + col];
                    if (act) x = x > 0.f ? x : 0.01f * x;
                    v[q] = x;
                }
            }
            if (a_src) {
                s1[mf][0] += v[0] * a_src[cl] + v[1] * a_src[cl + 1];
                s2[mf][0] += v[0] * a_dst[cl] + v[1] * a_dst[cl + 1];
                s1[mf][1] += v[2] * a_src[cl] + v[3] * a_src[cl + 1];
                s2[mf][1] += v[2] * a_dst[cl] + v[3] * a_dst[cl + 1];
            }
            if (outf) {
                if (cl + 1 < limit) {
                    *(float2*)(outf + (size_t)gr0 * ldout + nBase + cl) = make_float2(v[0], v[1]);
                    *(float2*)(outf + (size_t)(gr0 + 8) * ldout + nBase + cl) = make_float2(v[2], v[3]);
                } else if (cl < limit) {
                    outf[(size_t)gr0 * ldout + nBase + cl] = v[0];
                    outf[(size_t)(gr0 + 8) * ldout + nBase + cl] = v[2];
                }
            }
            if (outh && cl < limit) {
                *(__half2*)(outh + (size_t)gr0 * ldout + nBase + cl) = __floats2half2_rn(v[0], v[1]);
                *(__half2*)(outh + (size_t)(gr0 + 8) * ldout + nBase + cl) = __floats2half2_rn(v[2], v[3]);
            }
        }
    }
    if (a_src) {
        // warpN == head (N8 == 8: warp covers 64 cols == one head)
#pragma unroll
        for (int mf = 0; mf < 2; mf++)
#pragma unroll
            for (int hf = 0; hf < 2; hf++) {
                s1[mf][hf] += __shfl_xor_sync(0xFFFFFFFF, s1[mf][hf], 1);
                s1[mf][hf] += __shfl_xor_sync(0xFFFFFFFF, s1[mf][hf], 2);
                s2[mf][hf] += __shfl_xor_sync(0xFFFFFFFF, s2[mf][hf], 1);
                s2[mf][hf] += __shfl_xor_sync(0xFFFFFFFF, s2[mf][hf], 2);
            }
        if ((lane & 3) == 0) {
#pragma unroll
            for (int mf = 0; mf < 2; mf++)
#pragma unroll
                for (int hf = 0; hf < 2; hf++) {
                    int gr = mBase + warpM * 32 + mf * 16 + hf * 8 + lq;
                    als[gr * 4 + warpN] = s1[mf][hf];
                    ald[gr * 4 + warpN] = s2[mf][hf];
                }
        }
    }
}

// ======================= fused GAT aggregation (one warp per dst) ==========
// SINGLE PASS: softmax reference point = self-loop logit (mathematically
// exact for any reference; e - eself is bounded <<88 so exp cannot overflow).
// h is fp16 (L2-resident). Lane l handles channels [8l, 8(l+1)); head = l>>3.
__global__ __launch_bounds__(256)
void gat_agg(const int* __restrict__ offs, const int* __restrict__ srcarr,
             const float4* __restrict__ als4, const float4* __restrict__ ald4,
             const __half* __restrict__ h,
             const float* __restrict__ bias, int act,
             __half* __restrict__ out)
{
    __shared__ int    sh_src[8][32];
    __shared__ float4 sh_p[8][32];
    int w = (blockIdx.x * blockDim.x + threadIdx.x) >> 5;
    int ww = (threadIdx.x >> 5);
    int lane = threadIdx.x & 31;
    if (w >= NNODES) return;
    int n = w;
    int head = lane >> 3;
    int beg = offs[n], end = offs[n + 1];
    float4 aldn = ald4[n];
    float4 an = als4[n];
    float4 eself = leaky4_02(make_float4(an.x + aldn.x, an.y + aldn.y,
                                         an.z + aldn.z, an.w + aldn.w));
    // ---- single pass: p = exp(e - eself), sum, gather-accumulate ----
    float acc[8] = {0.f, 0.f, 0.f, 0.f, 0.f, 0.f, 0.f, 0.f};
    float4 psum = make_float4(1.f, 1.f, 1.f, 1.f);   // self loop: exp(0) = 1
    for (int base = beg; base < end; base += 32) {
        int j = base + lane;
        int valid = j < end;
        int s = 0;
        float4 p = make_float4(0.f, 0.f, 0.f, 0.f);
        if (valid) {
            s = srcarr[j];
            float4 a = als4[s];
            float4 e = leaky4_02(make_float4(a.x + aldn.x, a.y + aldn.y,
                                             a.z + aldn.z, a.w + aldn.w));
            p.x = __expf(e.x - eself.x); p.y = __expf(e.y - eself.y);
            p.z = __expf(e.z - eself.z); p.w = __expf(e.w - eself.w);
            psum.x += p.x; psum.y += p.y; psum.z += p.z; psum.w += p.w;
        }
        sh_src[ww][lane] = s;
        sh_p[ww][lane] = p;
        __syncwarp();
        int cnt = end - base; if (cnt > 32) cnt = 32;
#pragma unroll 4
        for (int jj = 0; jj < cnt; jj++) {
            int sj = sh_src[ww][jj];
            float4 pj = sh_p[ww][jj];
            float pv = (head == 0) ? pj.x : (head == 1) ? pj.y : (head == 2) ? pj.z : pj.w;
            uint4 raw = __ldg((const uint4*)(h + (size_t)sj * HC) + lane);
            float2 f0 = __half22float2(*(__half2*)&raw.x);
            float2 f1 = __half22float2(*(__half2*)&raw.y);
            float2 f2 = __half22float2(*(__half2*)&raw.z);
            float2 f3 = __half22float2(*(__half2*)&raw.w);
            acc[0] += pv * f0.x; acc[1] += pv * f0.y;
            acc[2] += pv * f1.x; acc[3] += pv * f1.y;
            acc[4] += pv * f2.x; acc[5] += pv * f2.y;
            acc[6] += pv * f3.x; acc[7] += pv * f3.y;
        }
        __syncwarp();
    }
    // psum started at 1 (self) in every lane; subtract the (31) duplicate 1s:
    // correct total = 1 + sum over edges. Reduce edge contributions only.
    psum.x -= 1.f; psum.y -= 1.f; psum.z -= 1.f; psum.w -= 1.f;
#pragma unroll
    for (int o = 16; o; o >>= 1) {
        psum.x += __shfl_xor_sync(0xFFFFFFFF, psum.x, o);
        psum.y += __shfl_xor_sync(0xFFFFFFFF, psum.y, o);
        psum.z += __shfl_xor_sync(0xFFFFFFFF, psum.z, o);
        psum.w += __shfl_xor_sync(0xFFFFFFFF, psum.w, o);
    }
    psum.x += 1.f; psum.y += 1.f; psum.z += 1.f; psum.w += 1.f;
    // self loop contribution: p = 1
    {
        uint4 raw = __ldg((const uint4*)(h + (size_t)n * HC) + lane);
        float2 f0 = __half22float2(*(__half2*)&raw.x);
        float2 f1 = __half22float2(*(__half2*)&raw.y);
        float2 f2 = __half22float2(*(__half2*)&raw.z);
        float2 f3 = __half22float2(*(__half2*)&raw.w);
        acc[0] += f0.x; acc[1] += f0.y;
        acc[2] += f1.x; acc[3] += f1.y;
        acc[4] += f2.x; acc[5] += f2.y;
        acc[6] += f3.x; acc[7] += f3.y;
    }
    // ---- epilogue: divide, bias, act, write fp16 ----
    float sH = (head == 0) ? psum.x : (head == 1) ? psum.y : (head == 2) ? psum.z : psum.w;
    float r = 1.f / sH;
    const float4* b4 = (const float4*)bias;   // channels 8l..8l+8 = b4[2l], b4[2l+1]
    float4 bA = b4[lane * 2], bB = b4[lane * 2 + 1];
    float v[8];
    v[0] = acc[0] * r + bA.x; v[1] = acc[1] * r + bA.y;
    v[2] = acc[2] * r + bA.z; v[3] = acc[3] * r + bA.w;
    v[4] = acc[4] * r + bB.x; v[5] = acc[5] * r + bB.y;
    v[6] = acc[6] * r + bB.z; v[7] = acc[7] * r + bB.w;
    if (act) {
#pragma unroll
        for (int q = 0; q < 8; q++) v[q] = v[q] > 0.f ? v[q] : 0.01f * v[q];
    }
    uint4 pack;
    *(__half2*)&pack.x = __floats2half2_rn(v[0], v[1]);
    *(__half2*)&pack.y = __floats2half2_rn(v[2], v[3]);
    *(__half2*)&pack.z = __floats2half2_rn(v[4], v[5]);
    *(__half2*)&pack.w = __floats2half2_rn(v[6], v[7]);
    *((uint4*)(out + (size_t)n * HC) + lane) = pack;
}

// ======================= host orchestration ================================
#define SMEM_N8  (2 * (16384 + 256 * 128))   // 98304
#define SMEM_N4  (2 * (16384 + 128 * 128))   // 65536

extern "C" void kernel_launch(void* const* d_in, const int* in_sizes, int n_in,
                              void* d_out, int out_size)
{
    const float* x    = (const float*)d_in[0];
    const void*  ei   = d_in[1];
    const float* root = (const float*)d_in[2];
    const float* W[3]  = {(const float*)d_in[3], (const float*)d_in[7],  (const float*)d_in[11]};
    const float* aS[3] = {(const float*)d_in[4], (const float*)d_in[8],  (const float*)d_in[12]};
    const float* aD[3] = {(const float*)d_in[5], (const float*)d_in[9],  (const float*)d_in[13]};
    const float* bb[3] = {(const float*)d_in[6], (const float*)d_in[10], (const float*)d_in[14]};
    const float* fc_w = (const float*)d_in[15];
    const float* fc_b = (const float*)d_in[16];
    const float* r_w1 = (const float*)d_in[17];
    const float* r_b1 = (const float*)d_in[18];
    const float* r_w2 = (const float*)d_in[19];
    const float* r_b2 = (const float*)d_in[20];
    const float* r_w3 = (const float*)d_in[21];
    const float* r_b3 = (const float*)d_in[22];

    float *p_als, *p_ald;
    __half *p_h, *p_A, *p_B, *p_rA, *p_r1, *p_r2;
    int *p_off, *p_cur, *p_srcarr, *p_flag;
    cudaGetSymbolAddress((void**)&p_h,   g_h);
    cudaGetSymbolAddress((void**)&p_A,   g_A);
    cudaGetSymbolAddress((void**)&p_als, g_als);
    cudaGetSymbolAddress((void**)&p_ald, g_ald);
    cudaGetSymbolAddress((void**)&p_off, g_off);
    cudaGetSymbolAddress((void**)&p_cur, g_cur);
    cudaGetSymbolAddress((void**)&p_srcarr, g_srcarr);
    cudaGetSymbolAddress((void**)&p_flag, g_is32);
    cudaGetSymbolAddress((void**)&p_B,   g_B);
    cudaGetSymbolAddress((void**)&p_rA,  g_rA);
    cudaGetSymbolAddress((void**)&p_r1,  g_r1);
    cudaGetSymbolAddress((void**)&p_r2,  g_r2);

    static int smem_set = 0;
    if (!smem_set) {
        cudaFuncSetAttribute(gemm_mma<8>, cudaFuncAttributeMaxDynamicSharedMemorySize, SMEM_N8);
        cudaFuncSetAttribute(gemm_mma<4>, cudaFuncAttributeMaxDynamicSharedMemorySize, SMEM_N4);
        smem_set = 1;
    }

    // ---- CSR build (once per call, reused by all 3 layers) ----
    cudaMemsetAsync(p_flag, 0, sizeof(int));
    detect_idx_kernel<<<(NEDGES + 255) / 256, 256>>>((const long long*)ei, p_flag);
    cudaMemsetAsync(p_cur, 0, NNODES * sizeof(int));
    hist_kernel<<<(NEDGES + 255) / 256, 256>>>(ei, p_flag, p_cur);
    scan_kernel<<<1, 1024>>>(p_cur, p_off);
    scatter_kernel<<<(NEDGES + 255) / 256, 256>>>(ei, p_flag, p_cur, p_srcarr);

    // ---- weight conversions (single launch) ----
    {
        ConvTable t;
        int base = 0;
        const float* srcs[7] = {W[0], W[1], W[2], fc_w, r_w1, r_w2, r_w3};
        int Ks[7]    = {80, 256, 256, 256, 60, 512, 512};
        int Ns[7]    = {256, 256, 256, 80, 512, 512, 60};
        int Kpads[7] = {128, 256, 256, 256, 64, 512, 512};
        int Npads[7] = {256, 256, 256, 128, 512, 512, 128};
        int offs7[7] = {OFF_W0, OFF_W1, OFF_W2, OFF_FC, OFF_R1, OFF_R2, OFF_R3};
        for (int i = 0; i < 7; i++) {
            t.d[i].src = srcs[i]; t.d[i].K = Ks[i]; t.d[i].N = Ns[i];
            t.d[i].Kpad = Kpads[i]; t.d[i].dstOff = offs7[i];
            t.d[i].base = base; t.d[i].elems = Npads[i] * Kpads[i];
            base += t.d[i].elems;
        }
        t.total = base;
        conv_B_all<<<(t.total + 255) / 256, 256>>>(t, p_B);
    }

    // x -> fp16, K padded 80->128
    conv_A_kernel<<<(NNODES * 128 + 255) / 256, 256>>>(x, p_A, NNODES, 80, 128);

    const int Kpad[3] = {128, 256, 256};
    const __half* Boff[3] = {p_B + OFF_W0, p_B + OFF_W1, p_B + OFF_W2};

    for (int L = 0; L < 3; L++) {
        gemm_mma<8><<<dim3(NNODES / 128, 1), 512, SMEM_N8>>>(
            p_A, Kpad[L], Boff[L],
            nullptr, p_h, 256, 256,
            nullptr, 0, aS[L], aD[L], p_als, p_ald);
        int act = (L < 2) ? 1 : 0;
        gat_agg<<<NNODES / 8, 256>>>(p_off, p_srcarr,
                                     (const float4*)p_als, (const float4*)p_ald,
                                     p_h, bb[L], act, p_A);
    }

    // rot = h @ fc_w + fc_b -> d_out[0 : N*80]  (NBLK=128, only 80 valid)
    float* rot = (float*)d_out;
    gemm_mma<4><<<dim3(NNODES / 128, 1), 512, SMEM_N4>>>(
        p_A, 256, p_B + OFF_FC,
        rot, nullptr, 80, 80,
        fc_b, 0, nullptr, nullptr, nullptr, nullptr);

    // root MLP
    conv_A_kernel<<<(4096 * 64 + 255) / 256, 256>>>(root, p_rA, 4096, 60, 64);
    gemm_mma<8><<<dim3(32, 2), 512, SMEM_N8>>>(
        p_rA, 64, p_B + OFF_R1,
        nullptr, p_r1, 512, 512,
        r_b1, 1, nullptr, nullptr, nullptr, nullptr);
    gemm_mma<8><<<dim3(32, 2), 512, SMEM_N8>>>(
        p_r1, 512, p_B + OFF_R2,
        nullptr, p_r2, 512, 512,
        r_b2, 1, nullptr, nullptr, nullptr, nullptr);
    float* root_out = rot + (size_t)NNODES * 80;
    gemm_mma<4><<<dim3(32, 1), 512, SMEM_N4>>>(
        p_r2, 512, p_B + OFF_R3,
        root_out, nullptr, 60, 60,
        r_b3, 0, nullptr, nullptr, nullptr, nullptr);
}

// round 14
// speedup vs baseline: 1.0803x; 1.0094x over previous
#include <cuda_runtime.h>
#include <cuda_fp16.h>
#include <cstdint>
#include <math.h>

// Problem constants (fixed by the dataset)
#define NNODES 102400
#define NEDGES 409600
#define HC 256
#define NH 4

// ======================= small helpers =====================================
__device__ __forceinline__ uint32_t smem_to_u32(const void* p) {
    uint32_t a;
    asm("{ .reg .u64 t; cvta.to.shared.u64 t, %1; cvt.u32.u64 %0, t; }" : "=r"(a) : "l"(p));
    return a;
}
__device__ __forceinline__ void cp16(uint32_t s, const void* g) {
    asm volatile("cp.async.cg.shared.global [%0], [%1], 16;" :: "r"(s), "l"(g));
}
__device__ __forceinline__ uint32_t smaddr(uint32_t base, int r, int c) {
    return base + r * 128 + ((((c >> 2) ^ (r & 7)) << 4)) + ((c & 3) << 2);
}
__device__ __forceinline__ void ldsm4(uint32_t* r, uint32_t a) {
    asm volatile("ldmatrix.sync.aligned.m8n8.x4.shared.b16 {%0,%1,%2,%3}, [%4];"
                 : "=r"(r[0]), "=r"(r[1]), "=r"(r[2]), "=r"(r[3]) : "r"(a));
}
__device__ __forceinline__ void mma_f16(float* d, uint32_t a0, uint32_t a1, uint32_t a2,
                                        uint32_t a3, uint32_t b0, uint32_t b1) {
    asm volatile(
        "mma.sync.aligned.m16n8k16.row.col.f32.f16.f16.f32 "
        "{%0,%1,%2,%3}, {%4,%5,%6,%7}, {%8,%9}, {%0,%1,%2,%3};"
        : "+f"(d[0]), "+f"(d[1]), "+f"(d[2]), "+f"(d[3])
        : "r"(a0), "r"(a1), "r"(a2), "r"(a3), "r"(b0), "r"(b1));
}
__device__ __forceinline__ float4 leaky4_02(float4 v) {
    v.x = v.x > 0.f ? v.x : 0.2f * v.x;
    v.y = v.y > 0.f ? v.y : 0.2f * v.y;
    v.z = v.z > 0.f ? v.z : 0.2f * v.z;
    v.w = v.w > 0.f ? v.w : 0.2f * v.w;
    return v;
}

// ======================= scratch (device globals) ==========================
__device__ __align__(16) __half g_h[(size_t)NNODES * HC];   // W-transformed feats
__device__ __align__(16) __half g_A[(size_t)NNODES * HC];   // layer input (aggregated)
__device__ __align__(16) float g_als[NNODES * NH];
__device__ __align__(16) float g_ald[NNODES * NH];
__device__ int g_off[NNODES + 1];
__device__ int g_cur[NNODES];
__device__ int g_srcarr[NEDGES];
__device__ int g_is32;
__device__ __align__(16) __half g_B[600000];
__device__ __align__(16) __half g_rA[4096 * 64];
__device__ __align__(16) __half g_r1[4096 * 512];
__device__ __align__(16) __half g_r2[4096 * 512];

// B buffer element offsets (B stored [Npad][Kpad], zero padded)
#define OFF_W0  0        // 256 x 128
#define OFF_W1  32768    // 256 x 256
#define OFF_W2  98304    // 256 x 256
#define OFF_FC  163840   // 128 x 256
#define OFF_R1  196608   // 512 x 64
#define OFF_R2  229376   // 512 x 512
#define OFF_R3  491520   // 128 x 512

// ======================= edge utilities ====================================
__device__ __forceinline__ void load_edge(const void* ei, int is32, int idx,
                                          int& src, int& dst) {
    if (is32) {
        src = ((const int*)ei)[idx];
        dst = ((const int*)ei)[NEDGES + idx];
    } else {
        src = (int)((const long long*)ei)[idx];
        dst = (int)((const long long*)ei)[NEDGES + idx];
    }
}

__global__ void detect_idx_kernel(const long long* ei, int* flag) {
    int i = blockIdx.x * blockDim.x + threadIdx.x;
    if (i >= NEDGES) return;
    long long v = ei[i];
    if (v < 0 || v >= (long long)NNODES) atomicOr(flag, 1);
}

__global__ void hist_kernel(const void* __restrict__ ei, const int* __restrict__ flag,
                            int* __restrict__ counts) {
    int i = blockIdx.x * blockDim.x + threadIdx.x;
    if (i >= NEDGES) return;
    int s, d;
    load_edge(ei, *flag, i, s, d);
    atomicAdd(&counts[d], 1);
}

// single block, 1024 threads, 100 counts each (1024*100 == NNODES)
__global__ void scan_kernel(int* __restrict__ counts_cursor, int* __restrict__ offs) {
    __shared__ int part[1024];
    int t = threadIdx.x;
    int base = t * 100;
    int sum = 0;
    for (int i = 0; i < 100; i++) sum += counts_cursor[base + i];
    part[t] = sum;
    __syncthreads();
    for (int d = 1; d < 1024; d <<= 1) {
        int v = (t >= d) ? part[t - d] : 0;
        __syncthreads();
        part[t] += v;
        __syncthreads();
    }
    int run = (t == 0) ? 0 : part[t - 1];
    for (int i = 0; i < 100; i++) {
        int c = counts_cursor[base + i];
        offs[base + i] = run;
        counts_cursor[base + i] = run;   // cursor for scatter
        run += c;
    }
    if (t == 1023) offs[NNODES] = run;
}

__global__ void scatter_kernel(const void* __restrict__ ei, const int* __restrict__ flag,
                               int* __restrict__ cursor, int* __restrict__ srcarr) {
    int i = blockIdx.x * blockDim.x + threadIdx.x;
    if (i >= NEDGES) return;
    int s, d;
    load_edge(ei, *flag, i, s, d);
    int pos = atomicAdd(&cursor[d], 1);
    srcarr[pos] = s;
}

// ======================= misc conversions ==================================
__global__ void conv_A_kernel(const float* __restrict__ A, __half* __restrict__ out,
                              int M, int K, int Kpad) {
    int i = blockIdx.x * blockDim.x + threadIdx.x;
    if (i >= M * Kpad) return;
    int m = i / Kpad, k = i - m * Kpad;
    float v = (k < K) ? A[(size_t)m * K + k] : 0.f;
    out[i] = __float2half(v);
}

// All weight tables converted in ONE launch. B [K,N] fp32 row-major ->
// Bt [Npad, Kpad] fp16 (zero padded), per-segment descriptors.
struct ConvDesc { const float* src; int K, N, Kpad, dstOff, base, elems; };
struct ConvTable { ConvDesc d[7]; int total; };
__global__ void conv_B_all(ConvTable t, __half* __restrict__ out) {
    int i = blockIdx.x * blockDim.x + threadIdx.x;
    if (i >= t.total) return;
    int seg = 0;
#pragma unroll
    for (int q = 0; q < 6; q++)
        if (i >= t.d[q].base + t.d[q].elems) seg = q + 1;
    const ConvDesc& dd = t.d[seg];
    int local = i - dd.base;
    int n = local / dd.Kpad, k = local - n * dd.Kpad;
    float v = (k < dd.K && n < dd.N) ? dd.src[(size_t)k * dd.N + n] : 0.f;
    out[dd.dstOff + local] = __float2half(v);
}

// ======================= fp16 mma.sync GEMM (ldmatrix loads) ===============
// 512 threads = 16 warps (4 warpM x 4 warpN), warp tile 32 x (N8*8).
// CTA tile 128 x NBLK (NBLK = N8*32). K chunks of 64, double buffered.
// N8=8: NBLK=256 (layer GEMMs, fused attn logits). N8=4: NBLK=128 (fc, r3).
template<int N8>
__global__ __launch_bounds__(512, 1)
void gemm_mma(const __half* __restrict__ A, int Kpad, const __half* __restrict__ B,
              float* outf, __half* outh, int nwrite, int ldout,
              const float* __restrict__ bias, int act,
              const float* __restrict__ a_src, const float* __restrict__ a_dst,
              float* als, float* ald)
{
    constexpr int NBLK = N8 * 32;
    constexpr uint32_t ASTAGE = 16384u;                 // 128 rows x 128B
    constexpr uint32_t BSTAGE = (uint32_t)NBLK * 128u;
    constexpr uint32_t STAGE = ASTAGE + BSTAGE;
    extern __shared__ char sm_raw[];
    uint32_t sb = smem_to_u32(sm_raw);
    int tid = threadIdx.x, wid = tid >> 5, lane = tid & 31;
    int warpM = wid & 3, warpN = wid >> 2;
    int mBase = blockIdx.x * 128;
    int nBase = blockIdx.y * NBLK;
    const int NC = Kpad >> 6;
    const int kp = lane & 3;
    const int lq = lane >> 2;

    // ldmatrix per-lane address components (loop-invariant)
    const int aRow = warpM * 32 + (lane & 15);          // A row for this lane
    const int aHi  = (lane >> 4) << 2;                  // +0 / +4 b32 cols
    const int bRow = warpN * N8 * 8 + ((lane >> 4) << 3) + (lane & 7);
    const int bHi  = ((lane >> 3) & 1) << 2;

    float acc[2][N8][4];
#pragma unroll
    for (int i = 0; i < 2; i++)
#pragma unroll
        for (int j = 0; j < N8; j++)
#pragma unroll
            for (int q = 0; q < 4; q++) acc[i][j][q] = 0.f;

    // ---- prologue: stage 0 ----
    {
        uint32_t base = sb;
#pragma unroll
        for (int i = 0; i < 2; i++) {                 // A: 1024 granules
            int u = tid + i * 512;
            int row = u >> 3, g = u & 7;
            const __half* src = A + (size_t)(mBase + row) * Kpad + g * 8;
            cp16(base + row * 128 + (((g ^ (row & 7)) << 4)), src);
        }
        for (int u = tid; u < NBLK * 8; u += 512) {   // B granules
            int row = u >> 3, g = u & 7;
            const __half* src = B + (size_t)(nBase + row) * Kpad + g * 8;
            cp16(base + ASTAGE + row * 128 + (((g ^ (row & 7)) << 4)), src);
        }
        asm volatile("cp.async.commit_group;" ::: "memory");
    }

    for (int c = 0; c < NC; c++) {
        if (c + 1 < NC) {
            uint32_t base = sb + ((c + 1) & 1) * STAGE;
            int ko = (c + 1) * 64;
#pragma unroll
            for (int i = 0; i < 2; i++) {
                int u = tid + i * 512;
                int row = u >> 3, g = u & 7;
                const __half* src = A + (size_t)(mBase + row) * Kpad + ko + g * 8;
                cp16(base + row * 128 + (((g ^ (row & 7)) << 4)), src);
            }
            for (int u = tid; u < NBLK * 8; u += 512) {
                int row = u >> 3, g = u & 7;
                const __half* src = B + (size_t)(nBase + row) * Kpad + ko + g * 8;
                cp16(base + ASTAGE + row * 128 + (((g ^ (row & 7)) << 4)), src);
            }
            asm volatile("cp.async.commit_group;" ::: "memory");
            asm volatile("cp.async.wait_group 1;" ::: "memory");
        } else {
            asm volatile("cp.async.wait_group 0;" ::: "memory");
        }
        __syncthreads();

        uint32_t aB = sb + (c & 1) * STAGE;
        uint32_t bB = aB + ASTAGE;
#pragma unroll
        for (int k16 = 0; k16 < 4; k16++) {
            int c0 = k16 * 8;
            uint32_t Af[2][4];
            ldsm4(Af[0], smaddr(aB, aRow,      c0 + aHi));
            ldsm4(Af[1], smaddr(aB, aRow + 16, c0 + aHi));
            uint32_t Bf[N8][2];
#pragma unroll
            for (int jp = 0; jp < N8 / 2; jp++) {
                uint32_t t[4];
                ldsm4(t, smaddr(bB, bRow + jp * 16, c0 + bHi));
                Bf[2 * jp][0] = t[0]; Bf[2 * jp][1] = t[1];
                Bf[2 * jp + 1][0] = t[2]; Bf[2 * jp + 1][1] = t[3];
            }
#pragma unroll
            for (int n8 = 0; n8 < N8; n8++)
#pragma unroll
                for (int mf = 0; mf < 2; mf++)
                    mma_f16(acc[mf][n8], Af[mf][0], Af[mf][1], Af[mf][2], Af[mf][3],
                            Bf[n8][0], Bf[n8][1]);
        }
        __syncthreads();
    }

    // ---- epilogue ----
    int limit = nwrite - nBase;
    float s1[2][2] = {{0.f, 0.f}, {0.f, 0.f}};
    float s2[2][2] = {{0.f, 0.f}, {0.f, 0.f}};
#pragma unroll
    for (int mf = 0; mf < 2; mf++) {
        int gr0 = mBase + warpM * 32 + mf * 16 + lq;
#pragma unroll
        for (int n8 = 0; n8 < N8; n8++) {
            int cl = warpN * N8 * 8 + n8 * 8 + kp * 2;
            float v[4];
#pragma unroll
            for (int q = 0; q < 4; q++) v[q] = acc[mf][n8][q];
#pragma unroll
            for (int q = 0; q < 4; q++) {
                int col = cl + (q & 1);
                if (col < limit) {
                    float x = v[q];
                    if (bias) x += bias[nBase + col];
                    if (act) x = x > 0.f ? x : 0.01f * x;
                    v[q] = x;
                }
            }
            if (a_src) {
                s1[mf][0] += v[0] * a_src[cl] + v[1] * a_src[cl + 1];
                s2[mf][0] += v[0] * a_dst[cl] + v[1] * a_dst[cl + 1];
                s1[mf][1] += v[2] * a_src[cl] + v[3] * a_src[cl + 1];
                s2[mf][1] += v[2] * a_dst[cl] + v[3] * a_dst[cl + 1];
            }
            if (outf) {
                if (cl + 1 < limit) {
                    *(float2*)(outf + (size_t)gr0 * ldout + nBase + cl) = make_float2(v[0], v[1]);
                    *(float2*)(outf + (size_t)(gr0 + 8) * ldout + nBase + cl) = make_float2(v[2], v[3]);
                } else if (cl < limit) {
                    outf[(size_t)gr0 * ldout + nBase + cl] = v[0];
                    outf[(size_t)(gr0 + 8) * ldout + nBase + cl] = v[2];
                }
            }
            if (outh && cl < limit) {
                *(__half2*)(outh + (size_t)gr0 * ldout + nBase + cl) = __floats2half2_rn(v[0], v[1]);
                *(__half2*)(outh + (size_t)(gr0 + 8) * ldout + nBase + cl) = __floats2half2_rn(v[2], v[3]);
            }
        }
    }
    if (a_src) {
        // warpN == head (N8 == 8: warp covers 64 cols == one head)
#pragma unroll
        for (int mf = 0; mf < 2; mf++)
#pragma unroll
            for (int hf = 0; hf < 2; hf++) {
                s1[mf][hf] += __shfl_xor_sync(0xFFFFFFFF, s1[mf][hf], 1);
                s1[mf][hf] += __shfl_xor_sync(0xFFFFFFFF, s1[mf][hf], 2);
                s2[mf][hf] += __shfl_xor_sync(0xFFFFFFFF, s2[mf][hf], 1);
                s2[mf][hf] += __shfl_xor_sync(0xFFFFFFFF, s2[mf][hf], 2);
            }
        if ((lane & 3) == 0) {
#pragma unroll
            for (int mf = 0; mf < 2; mf++)
#pragma unroll
                for (int hf = 0; hf < 2; hf++) {
                    int gr = mBase + warpM * 32 + mf * 16 + hf * 8 + lq;
                    als[gr * 4 + warpN] = s1[mf][hf];
                    ald[gr * 4 + warpN] = s2[mf][hf];
                }
        }
    }
}

// ======================= fused GAT aggregation (one warp per dst) ==========
// SINGLE PASS: softmax reference point = self-loop logit (mathematically
// exact for any reference; e - eself is bounded <<88 so exp cannot overflow).
// h is fp16 (L2-resident). Lane l handles channels [8l, 8(l+1)); head = l>>3.
__global__ __launch_bounds__(256)
void gat_agg(const int* __restrict__ offs, const int* __restrict__ srcarr,
             const float4* __restrict__ als4, const float4* __restrict__ ald4,
             const __half* __restrict__ h,
             const float* __restrict__ bias, int act,
             __half* __restrict__ out)
{
    __shared__ int    sh_src[8][32];
    __shared__ float4 sh_p[8][32];
    int w = (blockIdx.x * blockDim.x + threadIdx.x) >> 5;
    int ww = (threadIdx.x >> 5);
    int lane = threadIdx.x & 31;
    if (w >= NNODES) return;
    int n = w;
    int head = lane >> 3;
    int beg = offs[n], end = offs[n + 1];
    float4 aldn = ald4[n];
    float4 an = als4[n];
    float4 eself = leaky4_02(make_float4(an.x + aldn.x, an.y + aldn.y,
                                         an.z + aldn.z, an.w + aldn.w));
    // ---- single pass: p = exp(e - eself), sum, gather-accumulate ----
    float acc[8] = {0.f, 0.f, 0.f, 0.f, 0.f, 0.f, 0.f, 0.f};
    float4 psum = make_float4(1.f, 1.f, 1.f, 1.f);   // self loop: exp(0) = 1
    for (int base = beg; base < end; base += 32) {
        int j = base + lane;
        int valid = j < end;
        int s = 0;
        float4 p = make_float4(0.f, 0.f, 0.f, 0.f);
        if (valid) {
            s = srcarr[j];
            float4 a = als4[s];
            float4 e = leaky4_02(make_float4(a.x + aldn.x, a.y + aldn.y,
                                             a.z + aldn.z, a.w + aldn.w));
            p.x = __expf(e.x - eself.x); p.y = __expf(e.y - eself.y);
            p.z = __expf(e.z - eself.z); p.w = __expf(e.w - eself.w);
            psum.x += p.x; psum.y += p.y; psum.z += p.z; psum.w += p.w;
        }
        sh_src[ww][lane] = s;
        sh_p[ww][lane] = p;
        __syncwarp();
        int cnt = end - base; if (cnt > 32) cnt = 32;
#pragma unroll 4
        for (int jj = 0; jj < cnt; jj++) {
            int sj = sh_src[ww][jj];
            float4 pj = sh_p[ww][jj];
            float pv = (head == 0) ? pj.x : (head == 1) ? pj.y : (head == 2) ? pj.z : pj.w;
            uint4 raw = __ldg((const uint4*)(h + (size_t)sj * HC) + lane);
            float2 f0 = __half22float2(*(__half2*)&raw.x);
            float2 f1 = __half22float2(*(__half2*)&raw.y);
            float2 f2 = __half22float2(*(__half2*)&raw.z);
            float2 f3 = __half22float2(*(__half2*)&raw.w);
            acc[0] += pv * f0.x; acc[1] += pv * f0.y;
            acc[2] += pv * f1.x; acc[3] += pv * f1.y;
            acc[4] += pv * f2.x; acc[5] += pv * f2.y;
            acc[6] += pv * f3.x; acc[7] += pv * f3.y;
        }
        __syncwarp();
    }
    // psum started at 1 (self) in every lane; reduce edge contributions only.
    psum.x -= 1.f; psum.y -= 1.f; psum.z -= 1.f; psum.w -= 1.f;
#pragma unroll
    for (int o = 16; o; o >>= 1) {
        psum.x += __shfl_xor_sync(0xFFFFFFFF, psum.x, o);
        psum.y += __shfl_xor_sync(0xFFFFFFFF, psum.y, o);
        psum.z += __shfl_xor_sync(0xFFFFFFFF, psum.z, o);
        psum.w += __shfl_xor_sync(0xFFFFFFFF, psum.w, o);
    }
    psum.x += 1.f; psum.y += 1.f; psum.z += 1.f; psum.w += 1.f;
    // self loop contribution: p = 1
    {
        uint4 raw = __ldg((const uint4*)(h + (size_t)n * HC) + lane);
        float2 f0 = __half22float2(*(__half2*)&raw.x);
        float2 f1 = __half22float2(*(__half2*)&raw.y);
        float2 f2 = __half22float2(*(__half2*)&raw.z);
        float2 f3 = __half22float2(*(__half2*)&raw.w);
        acc[0] += f0.x; acc[1] += f0.y;
        acc[2] += f1.x; acc[3] += f1.y;
        acc[4] += f2.x; acc[5] += f2.y;
        acc[6] += f3.x; acc[7] += f3.y;
    }
    // ---- epilogue: divide, bias, act, write fp16 ----
    float sH = (head == 0) ? psum.x : (head == 1) ? psum.y : (head == 2) ? psum.z : psum.w;
    float r = 1.f / sH;
    const float4* b4 = (const float4*)bias;   // channels 8l..8l+8 = b4[2l], b4[2l+1]
    float4 bA = b4[lane * 2], bB = b4[lane * 2 + 1];
    float v[8];
    v[0] = acc[0] * r + bA.x; v[1] = acc[1] * r + bA.y;
    v[2] = acc[2] * r + bA.z; v[3] = acc[3] * r + bA.w;
    v[4] = acc[4] * r + bB.x; v[5] = acc[5] * r + bB.y;
    v[6] = acc[6] * r + bB.z; v[7] = acc[7] * r + bB.w;
    if (act) {
#pragma unroll
        for (int q = 0; q < 8; q++) v[q] = v[q] > 0.f ? v[q] : 0.01f * v[q];
    }
    uint4 pack;
    *(__half2*)&pack.x = __floats2half2_rn(v[0], v[1]);
    *(__half2*)&pack.y = __floats2half2_rn(v[2], v[3]);
    *(__half2*)&pack.z = __floats2half2_rn(v[4], v[5]);
    *(__half2*)&pack.w = __floats2half2_rn(v[6], v[7]);
    *((uint4*)(out + (size_t)n * HC) + lane) = pack;
}

// ======================= host orchestration ================================
#define SMEM_N8  (2 * (16384 + 256 * 128))   // 98304
#define SMEM_N4  (2 * (16384 + 128 * 128))   // 65536

extern "C" void kernel_launch(void* const* d_in, const int* in_sizes, int n_in,
                              void* d_out, int out_size)
{
    const float* x    = (const float*)d_in[0];
    const void*  ei   = d_in[1];
    const float* root = (const float*)d_in[2];
    const float* W[3]  = {(const float*)d_in[3], (const float*)d_in[7],  (const float*)d_in[11]};
    const float* aS[3] = {(const float*)d_in[4], (const float*)d_in[8],  (const float*)d_in[12]};
    const float* aD[3] = {(const float*)d_in[5], (const float*)d_in[9],  (const float*)d_in[13]};
    const float* bb[3] = {(const float*)d_in[6], (const float*)d_in[10], (const float*)d_in[14]};
    const float* fc_w = (const float*)d_in[15];
    const float* fc_b = (const float*)d_in[16];
    const float* r_w1 = (const float*)d_in[17];
    const float* r_b1 = (const float*)d_in[18];
    const float* r_w2 = (const float*)d_in[19];
    const float* r_b2 = (const float*)d_in[20];
    const float* r_w3 = (const float*)d_in[21];
    const float* r_b3 = (const float*)d_in[22];

    float *p_als, *p_ald;
    __half *p_h, *p_A, *p_B, *p_rA, *p_r1, *p_r2;
    int *p_off, *p_cur, *p_srcarr, *p_flag;
    cudaGetSymbolAddress((void**)&p_h,   g_h);
    cudaGetSymbolAddress((void**)&p_A,   g_A);
    cudaGetSymbolAddress((void**)&p_als, g_als);
    cudaGetSymbolAddress((void**)&p_ald, g_ald);
    cudaGetSymbolAddress((void**)&p_off, g_off);
    cudaGetSymbolAddress((void**)&p_cur, g_cur);
    cudaGetSymbolAddress((void**)&p_srcarr, g_srcarr);
    cudaGetSymbolAddress((void**)&p_flag, g_is32);
    cudaGetSymbolAddress((void**)&p_B,   g_B);
    cudaGetSymbolAddress((void**)&p_rA,  g_rA);
    cudaGetSymbolAddress((void**)&p_r1,  g_r1);
    cudaGetSymbolAddress((void**)&p_r2,  g_r2);

    static int smem_set = 0;
    if (!smem_set) {
        cudaFuncSetAttribute(gemm_mma<8>, cudaFuncAttributeMaxDynamicSharedMemorySize, SMEM_N8);
        cudaFuncSetAttribute(gemm_mma<4>, cudaFuncAttributeMaxDynamicSharedMemorySize, SMEM_N4);
        smem_set = 1;
    }

    // ---- CSR build (once per call, reused by all 3 layers) ----
    cudaMemsetAsync(p_flag, 0, sizeof(int));
    detect_idx_kernel<<<(NEDGES + 255) / 256, 256>>>((const long long*)ei, p_flag);
    cudaMemsetAsync(p_cur, 0, NNODES * sizeof(int));
    hist_kernel<<<(NEDGES + 255) / 256, 256>>>(ei, p_flag, p_cur);
    scan_kernel<<<1, 1024>>>(p_cur, p_off);
    scatter_kernel<<<(NEDGES + 255) / 256, 256>>>(ei, p_flag, p_cur, p_srcarr);

    // ---- weight conversions (single launch) ----
    {
        ConvTable t;
        int base = 0;
        const float* srcs[7] = {W[0], W[1], W[2], fc_w, r_w1, r_w2, r_w3};
        int Ks[7]    = {80, 256, 256, 256, 60, 512, 512};
        int Ns[7]    = {256, 256, 256, 80, 512, 512, 60};
        int Kpads[7] = {128, 256, 256, 256, 64, 512, 512};
        int Npads[7] = {256, 256, 256, 128, 512, 512, 128};
        int offs7[7] = {OFF_W0, OFF_W1, OFF_W2, OFF_FC, OFF_R1, OFF_R2, OFF_R3};
        for (int i = 0; i < 7; i++) {
            t.d[i].src = srcs[i]; t.d[i].K = Ks[i]; t.d[i].N = Ns[i];
            t.d[i].Kpad = Kpads[i]; t.d[i].dstOff = offs7[i];
            t.d[i].base = base; t.d[i].elems = Npads[i] * Kpads[i];
            base += t.d[i].elems;
        }
        t.total = base;
        conv_B_all<<<(t.total + 255) / 256, 256>>>(t, p_B);
    }

    // x -> fp16, K padded 80->128
    conv_A_kernel<<<(NNODES * 128 + 255) / 256, 256>>>(x, p_A, NNODES, 80, 128);

    const int Kpad[3] = {128, 256, 256};
    const __half* Boff[3] = {p_B + OFF_W0, p_B + OFF_W1, p_B + OFF_W2};

    for (int L = 0; L < 3; L++) {
        gemm_mma<8><<<dim3(NNODES / 128, 1), 512, SMEM_N8>>>(
            p_A, Kpad[L], Boff[L],
            nullptr, p_h, 256, 256,
            nullptr, 0, aS[L], aD[L], p_als, p_ald);
        int act = (L < 2) ? 1 : 0;
        gat_agg<<<NNODES / 8, 256>>>(p_off, p_srcarr,
                                     (const float4*)p_als, (const float4*)p_ald,
                                     p_h, bb[L], act, p_A);
    }

    // rot = h @ fc_w + fc_b -> d_out[0 : N*80]  (NBLK=128, only 80 valid)
    float* rot = (float*)d_out;
    gemm_mma<4><<<dim3(NNODES / 128, 1), 512, SMEM_N4>>>(
        p_A, 256, p_B + OFF_FC,
        rot, nullptr, 80, 80,
        fc_b, 0, nullptr, nullptr, nullptr, nullptr);

    // root MLP
    conv_A_kernel<<<(4096 * 64 + 255) / 256, 256>>>(root, p_rA, 4096, 60, 64);
    gemm_mma<8><<<dim3(32, 2), 512, SMEM_N8>>>(
        p_rA, 64, p_B + OFF_R1,
        nullptr, p_r1, 512, 512,
        r_b1, 1, nullptr, nullptr, nullptr, nullptr);
    gemm_mma<8><<<dim3(32, 2), 512, SMEM_N8>>>(
        p_r1, 512, p_B + OFF_R2,
        nullptr, p_r2, 512, 512,
        r_b2, 1, nullptr, nullptr, nullptr, nullptr);
    float* root_out = rot + (size_t)NNODES * 80;
    gemm_mma<4><<<dim3(32, 1), 512, SMEM_N4>>>(
        p_r2, 512, p_B + OFF_R3,
        root_out, nullptr, 60, 60,
        r_b3, 0, nullptr, nullptr, nullptr, nullptr);
}

// round 15
// speedup vs baseline: 1.1611x; 1.0748x over previous
#include <cuda_runtime.h>
#include <cuda_fp16.h>
#include <cstdint>
#include <math.h>

// Problem constants (fixed by the dataset)
#define NNODES 102400
#define NEDGES 409600
#define HC 256
#define NH 4

// ======================= small helpers =====================================
__device__ __forceinline__ uint32_t smem_to_u32(const void* p) {
    uint32_t a;
    asm("{ .reg .u64 t; cvta.to.shared.u64 t, %1; cvt.u32.u64 %0, t; }" : "=r"(a) : "l"(p));
    return a;
}
__device__ __forceinline__ void cp16(uint32_t s, const void* g) {
    asm volatile("cp.async.cg.shared.global [%0], [%1], 16;" :: "r"(s), "l"(g));
}
__device__ __forceinline__ uint32_t smaddr(uint32_t base, int r, int c) {
    return base + r * 128 + ((((c >> 2) ^ (r & 7)) << 4)) + ((c & 3) << 2);
}
__device__ __forceinline__ void ldsm4(uint32_t* r, uint32_t a) {
    asm volatile("ldmatrix.sync.aligned.m8n8.x4.shared.b16 {%0,%1,%2,%3}, [%4];"
                 : "=r"(r[0]), "=r"(r[1]), "=r"(r[2]), "=r"(r[3]) : "r"(a));
}
__device__ __forceinline__ void mma_f16(float* d, uint32_t a0, uint32_t a1, uint32_t a2,
                                        uint32_t a3, uint32_t b0, uint32_t b1) {
    asm volatile(
        "mma.sync.aligned.m16n8k16.row.col.f32.f16.f16.f32 "
        "{%0,%1,%2,%3}, {%4,%5,%6,%7}, {%8,%9}, {%0,%1,%2,%3};"
        : "+f"(d[0]), "+f"(d[1]), "+f"(d[2]), "+f"(d[3])
        : "r"(a0), "r"(a1), "r"(a2), "r"(a3), "r"(b0), "r"(b1));
}
__device__ __forceinline__ float4 leaky4_02(float4 v) {
    v.x = v.x > 0.f ? v.x : 0.2f * v.x;
    v.y = v.y > 0.f ? v.y : 0.2f * v.y;
    v.z = v.z > 0.f ? v.z : 0.2f * v.z;
    v.w = v.w > 0.f ? v.w : 0.2f * v.w;
    return v;
}

// ======================= scratch (device globals) ==========================
__device__ __align__(16) __half g_h[(size_t)NNODES * HC];   // W-transformed feats
__device__ __align__(16) __half g_A[(size_t)NNODES * HC];   // layer input (aggregated)
__device__ __align__(16) float g_als[NNODES * NH];
__device__ __align__(16) float g_ald[NNODES * NH];
__device__ int g_off[NNODES + 1];
__device__ int g_cur[NNODES];
__device__ int g_srcarr[NEDGES];
__device__ int g_is32;
__device__ __align__(16) __half g_B[600000];
__device__ __align__(16) __half g_rA[4096 * 64];
__device__ __align__(16) __half g_r1[4096 * 512];
__device__ __align__(16) __half g_r2[4096 * 512];

// B buffer element offsets (B stored [Npad][Kpad], zero padded)
#define OFF_W0  0        // 256 x 128
#define OFF_W1  32768    // 256 x 256
#define OFF_W2  98304    // 256 x 256
#define OFF_FC  163840   // 128 x 256
#define OFF_R1  196608   // 512 x 64
#define OFF_R2  229376   // 512 x 512
#define OFF_R3  491520   // 128 x 512

// ======================= edge utilities ====================================
__device__ __forceinline__ void load_edge(const void* ei, int is32, int idx,
                                          int& src, int& dst) {
    if (is32) {
        src = ((const int*)ei)[idx];
        dst = ((const int*)ei)[NEDGES + idx];
    } else {
        src = (int)((const long long*)ei)[idx];
        dst = (int)((const long long*)ei)[NEDGES + idx];
    }
}

__global__ void detect_idx_kernel(const long long* ei, int* flag) {
    int i = blockIdx.x * blockDim.x + threadIdx.x;
    if (i >= NEDGES) return;
    long long v = ei[i];
    if (v < 0 || v >= (long long)NNODES) atomicOr(flag, 1);
}

__global__ void hist_kernel(const void* __restrict__ ei, const int* __restrict__ flag,
                            int* __restrict__ counts) {
    int i = blockIdx.x * blockDim.x + threadIdx.x;
    if (i >= NEDGES) return;
    int s, d;
    load_edge(ei, *flag, i, s, d);
    atomicAdd(&counts[d], 1);
}

// single block, 1024 threads, 100 counts each (1024*100 == NNODES)
__global__ void scan_kernel(int* __restrict__ counts_cursor, int* __restrict__ offs) {
    __shared__ int part[1024];
    int t = threadIdx.x;
    int base = t * 100;
    int sum = 0;
    for (int i = 0; i < 100; i++) sum += counts_cursor[base + i];
    part[t] = sum;
    __syncthreads();
    for (int d = 1; d < 1024; d <<= 1) {
        int v = (t >= d) ? part[t - d] : 0;
        __syncthreads();
        part[t] += v;
        __syncthreads();
    }
    int run = (t == 0) ? 0 : part[t - 1];
    for (int i = 0; i < 100; i++) {
        int c = counts_cursor[base + i];
        offs[base + i] = run;
        counts_cursor[base + i] = run;   // cursor for scatter
        run += c;
    }
    if (t == 1023) offs[NNODES] = run;
}

__global__ void scatter_kernel(const void* __restrict__ ei, const int* __restrict__ flag,
                               int* __restrict__ cursor, int* __restrict__ srcarr) {
    int i = blockIdx.x * blockDim.x + threadIdx.x;
    if (i >= NEDGES) return;
    int s, d;
    load_edge(ei, *flag, i, s, d);
    int pos = atomicAdd(&cursor[d], 1);
    srcarr[pos] = s;
}

// ======================= misc conversions ==================================
__global__ void conv_A_kernel(const float* __restrict__ A, __half* __restrict__ out,
                              int M, int K, int Kpad) {
    int i = blockIdx.x * blockDim.x + threadIdx.x;
    if (i >= M * Kpad) return;
    int m = i / Kpad, k = i - m * Kpad;
    float v = (k < K) ? A[(size_t)m * K + k] : 0.f;
    out[i] = __float2half(v);
}

// All weight tables converted in ONE launch. B [K,N] fp32 row-major ->
// Bt [Npad, Kpad] fp16 (zero padded), per-segment descriptors.
struct ConvDesc { const float* src; int K, N, Kpad, dstOff, base, elems; };
struct ConvTable { ConvDesc d[7]; int total; };
__global__ void conv_B_all(ConvTable t, __half* __restrict__ out) {
    int i = blockIdx.x * blockDim.x + threadIdx.x;
    if (i >= t.total) return;
    int seg = 0;
#pragma unroll
    for (int q = 0; q < 6; q++)
        if (i >= t.d[q].base + t.d[q].elems) seg = q + 1;
    const ConvDesc& dd = t.d[seg];
    int local = i - dd.base;
    int n = local / dd.Kpad, k = local - n * dd.Kpad;
    float v = (k < dd.K && n < dd.N) ? dd.src[(size_t)k * dd.N + n] : 0.f;
    out[dd.dstOff + local] = __float2half(v);
}

// ======================= fp16 mma.sync GEMM ================================
// 256 threads = 8 warps (4 warpM x 2 warpN), warp tile 32 x 64 (N8=8 frags).
// CTA tile 128 x 128. Two CTAs co-resident per SM (64KB smem each) so chunk
// boundary stalls of one CTA overlap with the other's compute.
// K chunks of 64, double buffered, ldmatrix fragment loads.
#define N8 8
#define NBLK 128
__global__ __launch_bounds__(256, 2)
void gemm_mma(const __half* __restrict__ A, int Kpad, const __half* __restrict__ B,
              float* outf, __half* outh, int nwrite, int ldout,
              const float* __restrict__ bias, int act,
              const float* __restrict__ a_src, const float* __restrict__ a_dst,
              float* als, float* ald)
{
    constexpr uint32_t ASTAGE = 16384u;                 // 128 rows x 128B
    constexpr uint32_t BSTAGE = (uint32_t)NBLK * 128u;  // 16384
    constexpr uint32_t STAGE = ASTAGE + BSTAGE;         // 32768
    extern __shared__ char sm_raw[];
    uint32_t sb = smem_to_u32(sm_raw);
    int tid = threadIdx.x, wid = tid >> 5, lane = tid & 31;
    int warpM = wid & 3, warpN = wid >> 2;              // warpN in {0,1}
    int mBase = blockIdx.x * 128;
    int nBase = blockIdx.y * NBLK;
    const int NC = Kpad >> 6;
    const int kp = lane & 3;
    const int lq = lane >> 2;

    // ldmatrix per-lane address components (loop-invariant)
    const int aRow = warpM * 32 + (lane & 15);
    const int aHi  = (lane >> 4) << 2;
    const int bRow = warpN * 64 + ((lane >> 4) << 3) + (lane & 7);
    const int bHi  = ((lane >> 3) & 1) << 2;

    float acc[2][N8][4];
#pragma unroll
    for (int i = 0; i < 2; i++)
#pragma unroll
        for (int j = 0; j < N8; j++)
#pragma unroll
            for (int q = 0; q < 4; q++) acc[i][j][q] = 0.f;

    // ---- prologue: stage 0 ----
    {
        uint32_t base = sb;
#pragma unroll
        for (int i = 0; i < 4; i++) {                 // A: 1024 granules
            int u = tid + i * 256;
            int row = u >> 3, g = u & 7;
            const __half* src = A + (size_t)(mBase + row) * Kpad + g * 8;
            cp16(base + row * 128 + (((g ^ (row & 7)) << 4)), src);
        }
#pragma unroll
        for (int i = 0; i < 4; i++) {                 // B: 1024 granules
            int u = tid + i * 256;
            int row = u >> 3, g = u & 7;
            const __half* src = B + (size_t)(nBase + row) * Kpad + g * 8;
            cp16(base + ASTAGE + row * 128 + (((g ^ (row & 7)) << 4)), src);
        }
        asm volatile("cp.async.commit_group;" ::: "memory");
    }

    for (int c = 0; c < NC; c++) {
        if (c + 1 < NC) {
            uint32_t base = sb + ((c + 1) & 1) * STAGE;
            int ko = (c + 1) * 64;
#pragma unroll
            for (int i = 0; i < 4; i++) {
                int u = tid + i * 256;
                int row = u >> 3, g = u & 7;
                const __half* src = A + (size_t)(mBase + row) * Kpad + ko + g * 8;
                cp16(base + row * 128 + (((g ^ (row & 7)) << 4)), src);
            }
#pragma unroll
            for (int i = 0; i < 4; i++) {
                int u = tid + i * 256;
                int row = u >> 3, g = u & 7;
                const __half* src = B + (size_t)(nBase + row) * Kpad + ko + g * 8;
                cp16(base + ASTAGE + row * 128 + (((g ^ (row & 7)) << 4)), src);
            }
            asm volatile("cp.async.commit_group;" ::: "memory");
            asm volatile("cp.async.wait_group 1;" ::: "memory");
        } else {
            asm volatile("cp.async.wait_group 0;" ::: "memory");
        }
        __syncthreads();

        uint32_t aB = sb + (c & 1) * STAGE;
        uint32_t bB = aB + ASTAGE;
#pragma unroll
        for (int k16 = 0; k16 < 4; k16++) {
            int c0 = k16 * 8;
            uint32_t Af[2][4];
            ldsm4(Af[0], smaddr(aB, aRow,      c0 + aHi));
            ldsm4(Af[1], smaddr(aB, aRow + 16, c0 + aHi));
            uint32_t Bf[N8][2];
#pragma unroll
            for (int jp = 0; jp < N8 / 2; jp++) {
                uint32_t t[4];
                ldsm4(t, smaddr(bB, bRow + jp * 16, c0 + bHi));
                Bf[2 * jp][0] = t[0]; Bf[2 * jp][1] = t[1];
                Bf[2 * jp + 1][0] = t[2]; Bf[2 * jp + 1][1] = t[3];
            }
#pragma unroll
            for (int n8 = 0; n8 < N8; n8++)
#pragma unroll
                for (int mf = 0; mf < 2; mf++)
                    mma_f16(acc[mf][n8], Af[mf][0], Af[mf][1], Af[mf][2], Af[mf][3],
                            Bf[n8][0], Bf[n8][1]);
        }
        __syncthreads();
    }

    // ---- epilogue ----
    int limit = nwrite - nBase;
    float s1[2][2] = {{0.f, 0.f}, {0.f, 0.f}};
    float s2[2][2] = {{0.f, 0.f}, {0.f, 0.f}};
#pragma unroll
    for (int mf = 0; mf < 2; mf++) {
        int gr0 = mBase + warpM * 32 + mf * 16 + lq;
#pragma unroll
        for (int n8 = 0; n8 < N8; n8++) {
            int cl = warpN * 64 + n8 * 8 + kp * 2;
            float v[4];
#pragma unroll
            for (int q = 0; q < 4; q++) v[q] = acc[mf][n8][q];
#pragma unroll
            for (int q = 0; q < 4; q++) {
                int col = cl + (q & 1);
                if (col < limit) {
                    float x = v[q];
                    if (bias) x += bias[nBase + col];
                    if (act) x = x > 0.f ? x : 0.01f * x;
                    v[q] = x;
                }
            }
            if (a_src) {
                s1[mf][0] += v[0] * a_src[nBase + cl] + v[1] * a_src[nBase + cl + 1];
                s2[mf][0] += v[0] * a_dst[nBase + cl] + v[1] * a_dst[nBase + cl + 1];
                s1[mf][1] += v[2] * a_src[nBase + cl] + v[3] * a_src[nBase + cl + 1];
                s2[mf][1] += v[2] * a_dst[nBase + cl] + v[3] * a_dst[nBase + cl + 1];
            }
            if (outf) {
                if (cl + 1 < limit) {
                    *(float2*)(outf + (size_t)gr0 * ldout + nBase + cl) = make_float2(v[0], v[1]);
                    *(float2*)(outf + (size_t)(gr0 + 8) * ldout + nBase + cl) = make_float2(v[2], v[3]);
                } else if (cl < limit) {
                    outf[(size_t)gr0 * ldout + nBase + cl] = v[0];
                    outf[(size_t)(gr0 + 8) * ldout + nBase + cl] = v[2];
                }
            }
            if (outh && cl < limit) {
                *(__half2*)(outh + (size_t)gr0 * ldout + nBase + cl) = __floats2half2_rn(v[0], v[1]);
                *(__half2*)(outh + (size_t)(gr0 + 8) * ldout + nBase + cl) = __floats2half2_rn(v[2], v[3]);
            }
        }
    }
    if (a_src) {
        // warp covers exactly 64 cols = one head: head = nBase/64 + warpN
        int head = (nBase >> 6) + warpN;
#pragma unroll
        for (int mf = 0; mf < 2; mf++)
#pragma unroll
            for (int hf = 0; hf < 2; hf++) {
                s1[mf][hf] += __shfl_xor_sync(0xFFFFFFFF, s1[mf][hf], 1);
                s1[mf][hf] += __shfl_xor_sync(0xFFFFFFFF, s1[mf][hf], 2);
                s2[mf][hf] += __shfl_xor_sync(0xFFFFFFFF, s2[mf][hf], 1);
                s2[mf][hf] += __shfl_xor_sync(0xFFFFFFFF, s2[mf][hf], 2);
            }
        if ((lane & 3) == 0) {
#pragma unroll
            for (int mf = 0; mf < 2; mf++)
#pragma unroll
                for (int hf = 0; hf < 2; hf++) {
                    int gr = mBase + warpM * 32 + mf * 16 + hf * 8 + lq;
                    als[gr * 4 + head] = s1[mf][hf];
                    ald[gr * 4 + head] = s2[mf][hf];
                }
        }
    }
}

// ======================= fused GAT aggregation (one warp per dst) ==========
// SINGLE PASS: softmax reference point = self-loop logit (mathematically
// exact for any reference; e - eself is bounded <<88 so exp cannot overflow).
// h is fp16 (L2-resident). Lane l handles channels [8l, 8(l+1)); head = l>>3.
__global__ __launch_bounds__(256)
void gat_agg(const int* __restrict__ offs, const int* __restrict__ srcarr,
             const float4* __restrict__ als4, const float4* __restrict__ ald4,
             const __half* __restrict__ h,
             const float* __restrict__ bias, int act,
             __half* __restrict__ out)
{
    __shared__ int    sh_src[8][32];
    __shared__ float4 sh_p[8][32];
    int w = (blockIdx.x * blockDim.x + threadIdx.x) >> 5;
    int ww = (threadIdx.x >> 5);
    int lane = threadIdx.x & 31;
    if (w >= NNODES) return;
    int n = w;
    int head = lane >> 3;
    int beg = offs[n], end = offs[n + 1];
    float4 aldn = ald4[n];
    float4 an = als4[n];
    float4 eself = leaky4_02(make_float4(an.x + aldn.x, an.y + aldn.y,
                                         an.z + aldn.z, an.w + aldn.w));
    // ---- single pass: p = exp(e - eself), sum, gather-accumulate ----
    float acc[8] = {0.f, 0.f, 0.f, 0.f, 0.f, 0.f, 0.f, 0.f};
    float4 psum = make_float4(1.f, 1.f, 1.f, 1.f);   // self loop: exp(0) = 1
    for (int base = beg; base < end; base += 32) {
        int j = base + lane;
        int valid = j < end;
        int s = 0;
        float4 p = make_float4(0.f, 0.f, 0.f, 0.f);
        if (valid) {
            s = srcarr[j];
            float4 a = als4[s];
            float4 e = leaky4_02(make_float4(a.x + aldn.x, a.y + aldn.y,
                                             a.z + aldn.z, a.w + aldn.w));
            p.x = __expf(e.x - eself.x); p.y = __expf(e.y - eself.y);
            p.z = __expf(e.z - eself.z); p.w = __expf(e.w - eself.w);
            psum.x += p.x; psum.y += p.y; psum.z += p.z; psum.w += p.w;
        }
        sh_src[ww][lane] = s;
        sh_p[ww][lane] = p;
        __syncwarp();
        int cnt = end - base; if (cnt > 32) cnt = 32;
#pragma unroll 4
        for (int jj = 0; jj < cnt; jj++) {
            int sj = sh_src[ww][jj];
            float4 pj = sh_p[ww][jj];
            float pv = (head == 0) ? pj.x : (head == 1) ? pj.y : (head == 2) ? pj.z : pj.w;
            uint4 raw = __ldg((const uint4*)(h + (size_t)sj * HC) + lane);
            float2 f0 = __half22float2(*(__half2*)&raw.x);
            float2 f1 = __half22float2(*(__half2*)&raw.y);
            float2 f2 = __half22float2(*(__half2*)&raw.z);
            float2 f3 = __half22float2(*(__half2*)&raw.w);
            acc[0] += pv * f0.x; acc[1] += pv * f0.y;
            acc[2] += pv * f1.x; acc[3] += pv * f1.y;
            acc[4] += pv * f2.x; acc[5] += pv * f2.y;
            acc[6] += pv * f3.x; acc[7] += pv * f3.y;
        }
        __syncwarp();
    }
    // psum started at 1 (self) in every lane; reduce edge contributions only.
    psum.x -= 1.f; psum.y -= 1.f; psum.z -= 1.f; psum.w -= 1.f;
#pragma unroll
    for (int o = 16; o; o >>= 1) {
        psum.x += __shfl_xor_sync(0xFFFFFFFF, psum.x, o);
        psum.y += __shfl_xor_sync(0xFFFFFFFF, psum.y, o);
        psum.z += __shfl_xor_sync(0xFFFFFFFF, psum.z, o);
        psum.w += __shfl_xor_sync(0xFFFFFFFF, psum.w, o);
    }
    psum.x += 1.f; psum.y += 1.f; psum.z += 1.f; psum.w += 1.f;
    // self loop contribution: p = 1
    {
        uint4 raw = __ldg((const uint4*)(h + (size_t)n * HC) + lane);
        float2 f0 = __half22float2(*(__half2*)&raw.x);
        float2 f1 = __half22float2(*(__half2*)&raw.y);
        float2 f2 = __half22float2(*(__half2*)&raw.z);
        float2 f3 = __half22float2(*(__half2*)&raw.w);
        acc[0] += f0.x; acc[1] += f0.y;
        acc[2] += f1.x; acc[3] += f1.y;
        acc[4] += f2.x; acc[5] += f2.y;
        acc[6] += f3.x; acc[7] += f3.y;
    }
    // ---- epilogue: divide, bias, act, write fp16 ----
    float sH = (head == 0) ? psum.x : (head == 1) ? psum.y : (head == 2) ? psum.z : psum.w;
    float r = 1.f / sH;
    const float4* b4 = (const float4*)bias;   // channels 8l..8l+8 = b4[2l], b4[2l+1]
    float4 bA = b4[lane * 2], bB = b4[lane * 2 + 1];
    float v[8];
    v[0] = acc[0] * r + bA.x; v[1] = acc[1] * r + bA.y;
    v[2] = acc[2] * r + bA.z; v[3] = acc[3] * r + bA.w;
    v[4] = acc[4] * r + bB.x; v[5] = acc[5] * r + bB.y;
    v[6] = acc[6] * r + bB.z; v[7] = acc[7] * r + bB.w;
    if (act) {
#pragma unroll
        for (int q = 0; q < 8; q++) v[q] = v[q] > 0.f ? v[q] : 0.01f * v[q];
    }
    uint4 pack;
    *(__half2*)&pack.x = __floats2half2_rn(v[0], v[1]);
    *(__half2*)&pack.y = __floats2half2_rn(v[2], v[3]);
    *(__half2*)&pack.z = __floats2half2_rn(v[4], v[5]);
    *(__half2*)&pack.w = __floats2half2_rn(v[6], v[7]);
    *((uint4*)(out + (size_t)n * HC) + lane) = pack;
}

// ======================= host orchestration ================================
#define GEMM_SMEM (2 * 32768)   // 65536 per CTA -> 2 CTAs/SM

extern "C" void kernel_launch(void* const* d_in, const int* in_sizes, int n_in,
                              void* d_out, int out_size)
{
    const float* x    = (const float*)d_in[0];
    const void*  ei   = d_in[1];
    const float* root = (const float*)d_in[2];
    const float* W[3]  = {(const float*)d_in[3], (const float*)d_in[7],  (const float*)d_in[11]};
    const float* aS[3] = {(const float*)d_in[4], (const float*)d_in[8],  (const float*)d_in[12]};
    const float* aD[3] = {(const float*)d_in[5], (const float*)d_in[9],  (const float*)d_in[13]};
    const float* bb[3] = {(const float*)d_in[6], (const float*)d_in[10], (const float*)d_in[14]};
    const float* fc_w = (const float*)d_in[15];
    const float* fc_b = (const float*)d_in[16];
    const float* r_w1 = (const float*)d_in[17];
    const float* r_b1 = (const float*)d_in[18];
    const float* r_w2 = (const float*)d_in[19];
    const float* r_b2 = (const float*)d_in[20];
    const float* r_w3 = (const float*)d_in[21];
    const float* r_b3 = (const float*)d_in[22];

    float *p_als, *p_ald;
    __half *p_h, *p_A, *p_B, *p_rA, *p_r1, *p_r2;
    int *p_off, *p_cur, *p_srcarr, *p_flag;
    cudaGetSymbolAddress((void**)&p_h,   g_h);
    cudaGetSymbolAddress((void**)&p_A,   g_A);
    cudaGetSymbolAddress((void**)&p_als, g_als);
    cudaGetSymbolAddress((void**)&p_ald, g_ald);
    cudaGetSymbolAddress((void**)&p_off, g_off);
    cudaGetSymbolAddress((void**)&p_cur, g_cur);
    cudaGetSymbolAddress((void**)&p_srcarr, g_srcarr);
    cudaGetSymbolAddress((void**)&p_flag, g_is32);
    cudaGetSymbolAddress((void**)&p_B,   g_B);
    cudaGetSymbolAddress((void**)&p_rA,  g_rA);
    cudaGetSymbolAddress((void**)&p_r1,  g_r1);
    cudaGetSymbolAddress((void**)&p_r2,  g_r2);

    static int smem_set = 0;
    if (!smem_set) {
        cudaFuncSetAttribute(gemm_mma, cudaFuncAttributeMaxDynamicSharedMemorySize, GEMM_SMEM);
        smem_set = 1;
    }

    // ---- CSR build (once per call, reused by all 3 layers) ----
    cudaMemsetAsync(p_flag, 0, sizeof(int));
    detect_idx_kernel<<<(NEDGES + 255) / 256, 256>>>((const long long*)ei, p_flag);
    cudaMemsetAsync(p_cur, 0, NNODES * sizeof(int));
    hist_kernel<<<(NEDGES + 255) / 256, 256>>>(ei, p_flag, p_cur);
    scan_kernel<<<1, 1024>>>(p_cur, p_off);
    scatter_kernel<<<(NEDGES + 255) / 256, 256>>>(ei, p_flag, p_cur, p_srcarr);

    // ---- weight conversions (single launch) ----
    {
        ConvTable t;
        int base = 0;
        const float* srcs[7] = {W[0], W[1], W[2], fc_w, r_w1, r_w2, r_w3};
        int Ks[7]    = {80, 256, 256, 256, 60, 512, 512};
        int Ns[7]    = {256, 256, 256, 80, 512, 512, 60};
        int Kpads[7] = {128, 256, 256, 256, 64, 512, 512};
        int Npads[7] = {256, 256, 256, 128, 512, 512, 128};
        int offs7[7] = {OFF_W0, OFF_W1, OFF_W2, OFF_FC, OFF_R1, OFF_R2, OFF_R3};
        for (int i = 0; i < 7; i++) {
            t.d[i].src = srcs[i]; t.d[i].K = Ks[i]; t.d[i].N = Ns[i];
            t.d[i].Kpad = Kpads[i]; t.d[i].dstOff = offs7[i];
            t.d[i].base = base; t.d[i].elems = Npads[i] * Kpads[i];
            base += t.d[i].elems;
        }
        t.total = base;
        conv_B_all<<<(t.total + 255) / 256, 256>>>(t, p_B);
    }

    // x -> fp16, K padded 80->128
    conv_A_kernel<<<(NNODES * 128 + 255) / 256, 256>>>(x, p_A, NNODES, 80, 128);

    const int Kpad[3] = {128, 256, 256};
    const __half* Boff[3] = {p_B + OFF_W0, p_B + OFF_W1, p_B + OFF_W2};

    for (int L = 0; L < 3; L++) {
        gemm_mma<<<dim3(NNODES / 128, 2), 256, GEMM_SMEM>>>(
            p_A, Kpad[L], Boff[L],
            nullptr, p_h, 256, 256,
            nullptr, 0, aS[L], aD[L], p_als, p_ald);
        int act = (L < 2) ? 1 : 0;
        gat_agg<<<NNODES / 8, 256>>>(p_off, p_srcarr,
                                     (const float4*)p_als, (const float4*)p_ald,
                                     p_h, bb[L], act, p_A);
    }

    // rot = h @ fc_w + fc_b -> d_out[0 : N*80]  (NBLK=128, only 80 valid)
    float* rot = (float*)d_out;
    gemm_mma<<<dim3(NNODES / 128, 1), 256, GEMM_SMEM>>>(
        p_A, 256, p_B + OFF_FC,
        rot, nullptr, 80, 80,
        fc_b, 0, nullptr, nullptr, nullptr, nullptr);

    // root MLP
    conv_A_kernel<<<(4096 * 64 + 255) / 256, 256>>>(root, p_rA, 4096, 60, 64);
    gemm_mma<<<dim3(32, 4), 256, GEMM_SMEM>>>(
        p_rA, 64, p_B + OFF_R1,
        nullptr, p_r1, 512, 512,
        r_b1, 1, nullptr, nullptr, nullptr, nullptr);
    gemm_mma<<<dim3(32, 4), 256, GEMM_SMEM>>>(
        p_r1, 512, p_B + OFF_R2,
        nullptr, p_r2, 512, 512,
        r_b2, 1, nullptr, nullptr, nullptr, nullptr);
    float* root_out = rot + (size_t)NNODES * 80;
    gemm_mma<<<dim3(32, 1), 256, GEMM_SMEM>>>(
        p_r2, 512, p_B + OFF_R3,
        root_out, nullptr, 60, 60,
        r_b3, 0, nullptr, nullptr, nullptr, nullptr);
}